// round 1
// baseline (speedup 1.0000x reference)
#include <cuda_runtime.h>
#include <math.h>

#define NE_MAX 200000
#define NA_MAX 1600000

// ---- static scratch (no cudaMalloc allowed) ----
__device__ float g_P0[(size_t)NE_MAX * 128];          // nbr_fea @ W_full[40:104]
__device__ float g_P1[(size_t)NE_MAX * 128];          // nbr_fea @ W_full[104:168]
__device__ float g_gbuf[(size_t)NA_MAX * 128];        // gated (pre-norm)
__device__ float g_csum[256 * 128];
__device__ float g_csumsq[256 * 128];
__device__ unsigned int g_ccnt[256];
__device__ float g_a1[256 * 128];
__device__ float g_b1[256 * 128];
__device__ float g_summed[(size_t)NE_MAX * 64];
__device__ unsigned int g_acnt[NE_MAX];               // angles per src edge
__device__ float g_esum[256 * 64];
__device__ float g_esumsq[256 * 64];
__device__ unsigned int g_ecnt[256];
__device__ float g_a2[256 * 64];
__device__ float g_b2[256 * 64];

// ---- K0: zero accumulators (graph replays must be deterministic) ----
__global__ void k_zero(int n_edges) {
    int i = blockIdx.x * blockDim.x + threadIdx.x;
    int stride = gridDim.x * blockDim.x;
    for (int k = i; k < n_edges * 64; k += stride) g_summed[k] = 0.f;
    for (int k = i; k < n_edges; k += stride) g_acnt[k] = 0u;
    for (int k = i; k < 256 * 128; k += stride) { g_csum[k] = 0.f; g_csumsq[k] = 0.f; }
    for (int k = i; k < 256 * 64; k += stride) { g_esum[k] = 0.f; g_esumsq[k] = 0.f; }
    for (int k = i; k < 256; k += stride) { g_ccnt[k] = 0u; g_ecnt[k] = 0u; }
}

// ---- K1: P0/P1 = nbr_fea @ W_full halves. blockIdx.y selects half. ----
__global__ void k_precompute(const float* __restrict__ nbr,
                             const float* __restrict__ W_full, int n_edges) {
    int j = threadIdx.x;          // output channel 0..127
    int half = blockIdx.y;        // 0 -> rows 40..103, 1 -> rows 104..167
    float w[64];
    const float* wb = W_full + (size_t)(40 + half * 64) * 128 + j;
#pragma unroll
    for (int k = 0; k < 64; k++) w[k] = wb[(size_t)k * 128];
    float* P = half ? g_P1 : g_P0;
    __shared__ float4 snb[16];
    for (int e = blockIdx.x; e < n_edges; e += gridDim.x) {
        if (j < 16) snb[j] = ((const float4*)(nbr + (size_t)e * 64))[j];
        __syncthreads();
        float acc = 0.f;
#pragma unroll
        for (int k = 0; k < 16; k++) {
            float4 v = snb[k];
            acc += v.x * w[4 * k] + v.y * w[4 * k + 1] + v.z * w[4 * k + 2] + v.w * w[4 * k + 3];
        }
        P[(size_t)e * 128 + j] = acc;
        __syncthreads();
    }
}

// ---- K2: gated = angle@W[:40] + P0[i0] + P1[i1]; store; crystal stats (sorted seg) ----
__global__ void k_angle_main(const float* __restrict__ angle_fea,
                             const int* __restrict__ anb,
                             const int* __restrict__ ca,
                             const float* __restrict__ W_full, int n_angles) {
    const int CHUNK = 512;
    int j = threadIdx.x;  // 128
    int a0 = blockIdx.x * CHUNK;
    if (a0 >= n_angles) return;
    int aend = min(a0 + CHUNK, n_angles);
    float w[40];
#pragma unroll
    for (int k = 0; k < 40; k++) w[k] = W_full[(size_t)k * 128 + j];
    __shared__ float4 saf[10];
    __shared__ int sidx[3];
    float lsum = 0.f, lsq = 0.f;
    int lcnt = 0;
    int cur = ca[a0];
    for (int a = a0; a < aend; a++) {
        if (j < 10) saf[j] = ((const float4*)(angle_fea + (size_t)a * 40))[j];
        if (j == 0) {
            sidx[0] = anb[2 * (size_t)a];
            sidx[1] = anb[2 * (size_t)a + 1];
            sidx[2] = ca[a];
        }
        __syncthreads();
        int c = sidx[2];
        int i0 = sidx[0], i1 = sidx[1];
        if (c != cur) {
            atomicAdd(&g_csum[cur * 128 + j], lsum);
            atomicAdd(&g_csumsq[cur * 128 + j], lsq);
            if (j == 0) atomicAdd(&g_ccnt[cur], (unsigned)lcnt);
            lsum = 0.f; lsq = 0.f; lcnt = 0; cur = c;
        }
        float acc = g_P0[(size_t)i0 * 128 + j] + g_P1[(size_t)i1 * 128 + j];
#pragma unroll
        for (int k = 0; k < 10; k++) {
            float4 v = saf[k];
            acc += v.x * w[4 * k] + v.y * w[4 * k + 1] + v.z * w[4 * k + 2] + v.w * w[4 * k + 3];
        }
        g_gbuf[(size_t)a * 128 + j] = acc;
        lsum += acc; lsq += acc * acc; lcnt++;
        __syncthreads();
    }
    atomicAdd(&g_csum[cur * 128 + j], lsum);
    atomicAdd(&g_csumsq[cur * 128 + j], lsq);
    if (j == 0) atomicAdd(&g_ccnt[cur], (unsigned)lcnt);
}

// ---- K3: finalize crystal_norm1 affine ----
__global__ void k_stats1(const float* __restrict__ gn1_g, const float* __restrict__ gn1_b) {
    int c = blockIdx.x, j = threadIdx.x;  // 256 x 128
    float cnt = fmaxf((float)g_ccnt[c], 1.f);
    float mean = g_csum[c * 128 + j] / cnt;
    float var = fmaxf(g_csumsq[c * 128 + j] / cnt - mean * mean, 0.f);
    float inv = rsqrtf(var + 1e-5f);
    float a = gn1_g[j] * inv;
    g_a1[c * 128 + j] = a;
    g_b1[c * 128 + j] = gn1_b[j] - mean * a;
}

// ---- K4: normalize, core/filt, scatter-add into summed[src] (warp per angle) ----
__global__ void k_angle_scatter(const int* __restrict__ anb,
                                const int* __restrict__ ca,
                                const float* __restrict__ W_mask, int n_angles) {
    int w = threadIdx.x >> 5;
    int l = threadIdx.x & 31;
    int stride = (blockDim.x >> 5) * gridDim.x;
    for (int a = blockIdx.x * (blockDim.x >> 5) + w; a < n_angles; a += stride) {
        float4 gv = ((const float4*)(g_gbuf + (size_t)a * 128))[l];
        int c = ca[a];
        float4 av = ((const float4*)(g_a1 + (size_t)c * 128))[l];
        float4 bv = ((const float4*)(g_b1 + (size_t)c * 128))[l];
        float x0 = gv.x * av.x + bv.x;
        float x1 = gv.y * av.y + bv.y;
        float x2 = gv.z * av.z + bv.z;
        float x3 = gv.w * av.w + bv.w;
        float part = 0.f;
        if (l >= 16) {  // lanes 16..31 hold channels 64..127 (filt half)
            float4 m = ((const float4*)W_mask)[l - 16];
            part = x0 * m.x + x1 * m.y + x2 * m.z + x3 * m.w;
        }
#pragma unroll
        for (int off = 16; off; off >>= 1) part += __shfl_xor_sync(0xffffffffu, part, off);
        float filt = tanhf(part);
        if (l < 16) {  // lanes 0..15 hold channels 0..63 (core half)
            int src = anb[2 * (size_t)a];
            float* dst = g_summed + (size_t)src * 64 + 4 * l;
            atomicAdd(dst + 0, filt * fmaxf(x0, 0.f));
            atomicAdd(dst + 1, filt * fmaxf(x1, 0.f));
            atomicAdd(dst + 2, filt * fmaxf(x2, 0.f));
            atomicAdd(dst + 3, filt * fmaxf(x3, 0.f));
            if (l == 0) atomicAdd(&g_acnt[src], 1u);
        }
    }
}

// ---- K5: per-crystal stats over edges for crystal_norm2 (sorted seg) ----
__global__ void k_edge_stats(const int* __restrict__ ce, int n_edges) {
    const int CHUNK = 128;
    int j = threadIdx.x;  // 64
    int e0 = blockIdx.x * CHUNK;
    if (e0 >= n_edges) return;
    int eend = min(e0 + CHUNK, n_edges);
    float lsum = 0.f, lsq = 0.f;
    int lcnt = 0;
    int cur = ce[e0];
    for (int e = e0; e < eend; e++) {
        int c = ce[e];
        if (c != cur) {
            atomicAdd(&g_esum[cur * 64 + j], lsum);
            atomicAdd(&g_esumsq[cur * 64 + j], lsq);
            if (j == 0) atomicAdd(&g_ecnt[cur], (unsigned)lcnt);
            lsum = 0.f; lsq = 0.f; lcnt = 0; cur = c;
        }
        float cnt = fmaxf((float)g_acnt[e], 1.f);
        float v = g_summed[(size_t)e * 64 + j] / cnt;
        lsum += v; lsq += v * v; lcnt++;
    }
    atomicAdd(&g_esum[cur * 64 + j], lsum);
    atomicAdd(&g_esumsq[cur * 64 + j], lsq);
    if (j == 0) atomicAdd(&g_ecnt[cur], (unsigned)lcnt);
}

// ---- K6: finalize crystal_norm2 affine ----
__global__ void k_stats2(const float* __restrict__ gn2_g, const float* __restrict__ gn2_b) {
    int c = blockIdx.x, j = threadIdx.x;  // 256 x 64
    float cnt = fmaxf((float)g_ecnt[c], 1.f);
    float mean = g_esum[c * 64 + j] / cnt;
    float var = fmaxf(g_esumsq[c * 64 + j] / cnt - mean * mean, 0.f);
    float inv = rsqrtf(var + 1e-5f);
    float a = gn2_g[j] * inv;
    g_a2[c * 64 + j] = a;
    g_b2[c * 64 + j] = gn2_b[j] - mean * a;
}

// ---- K7: normalize edges, two residual MLPs, final relu ----
__global__ void k_final(const float* __restrict__ nbr, const int* __restrict__ ce,
                        const float* __restrict__ W1a, const float* __restrict__ b1a,
                        const float* __restrict__ W2a, const float* __restrict__ b2a,
                        const float* __restrict__ W1b, const float* __restrict__ b1b,
                        const float* __restrict__ W2b, const float* __restrict__ b2b,
                        float* __restrict__ out, int n_edges) {
    __shared__ float sW1a[64 * 32], sW2a[32 * 64], sW1b[64 * 32], sW2b[32 * 64];
    __shared__ float sb1a[32], sb2a[64], sb1b[32], sb2b[64];
    __shared__ float sh_h[4][64];
    __shared__ float sh_r[4][32];
    int t = threadIdx.x;  // 256
    for (int k = t; k < 2048; k += 256) {
        sW1a[k] = W1a[k]; sW2a[k] = W2a[k]; sW1b[k] = W1b[k]; sW2b[k] = W2b[k];
    }
    if (t < 32) { sb1a[t] = b1a[t]; sb1b[t] = b1b[t]; }
    if (t < 64) { sb2a[t] = b2a[t]; sb2b[t] = b2b[t]; }
    __syncthreads();
    int g = t >> 6, j = t & 63;
    int total = (n_edges + 3) >> 2;  // 4-edge groups; uniform loop count per block
    for (int blk = blockIdx.x; blk < total; blk += gridDim.x) {
        int e = blk * 4 + g;
        bool valid = e < n_edges;
        float h = 0.f;
        if (valid) {
            float cnt = fmaxf((float)g_acnt[e], 1.f);
            int c = ce[e];
            h = (g_summed[(size_t)e * 64 + j] / cnt) * g_a2[c * 64 + j] + g_b2[c * 64 + j];
        }
        sh_h[g][j] = h;
        __syncthreads();
        if (j < 32) {
            float acc = sb1a[j];
#pragma unroll
            for (int k = 0; k < 64; k++) acc += sh_h[g][k] * sW1a[k * 32 + j];
            sh_r[g][j] = fmaxf(acc, 0.f);
        }
        __syncthreads();
        {
            float acc = sb2a[j];
#pragma unroll
            for (int m = 0; m < 32; m++) acc += sh_r[g][m] * sW2a[m * 64 + j];
            h += acc;
            sh_h[g][j] = h;
        }
        __syncthreads();
        if (j < 32) {
            float acc = sb1b[j];
#pragma unroll
            for (int k = 0; k < 64; k++) acc += sh_h[g][k] * sW1b[k * 32 + j];
            sh_r[g][j] = fmaxf(acc, 0.f);
        }
        __syncthreads();
        {
            float acc = sb2b[j];
#pragma unroll
            for (int m = 0; m < 32; m++) acc += sh_r[g][m] * sW2b[m * 64 + j];
            h += acc;
        }
        if (valid)
            out[(size_t)e * 64 + j] =
                0.7071067811865476f * fmaxf(nbr[(size_t)e * 64 + j] + h, 0.f);
        __syncthreads();
    }
}

extern "C" void kernel_launch(void* const* d_in, const int* in_sizes, int n_in,
                              void* d_out, int out_size) {
    const float* nbr       = (const float*)d_in[0];
    const float* angle_fea = (const float*)d_in[1];
    const int*   anb       = (const int*)d_in[2];
    const int*   ce        = (const int*)d_in[3];
    const int*   ca        = (const int*)d_in[4];
    const float* W_full    = (const float*)d_in[5];
    const float* W_mask    = (const float*)d_in[6];
    const float* gn1_g     = (const float*)d_in[7];
    const float* gn1_b     = (const float*)d_in[8];
    const float* gn2_g     = (const float*)d_in[9];
    const float* gn2_b     = (const float*)d_in[10];
    const float* W1a       = (const float*)d_in[11];
    const float* b1a       = (const float*)d_in[12];
    const float* W2a       = (const float*)d_in[13];
    const float* b2a       = (const float*)d_in[14];
    const float* W1b       = (const float*)d_in[15];
    const float* b1b       = (const float*)d_in[16];
    const float* W2b       = (const float*)d_in[17];
    const float* b2b       = (const float*)d_in[18];
    float* out = (float*)d_out;

    int n_edges  = in_sizes[0] / 64;
    int n_angles = in_sizes[1] / 40;

    k_zero<<<2048, 256>>>(n_edges);
    dim3 g1(512, 2);
    k_precompute<<<g1, 128>>>(nbr, W_full, n_edges);
    int nblk2 = (n_angles + 511) / 512;
    k_angle_main<<<nblk2, 128>>>(angle_fea, anb, ca, W_full, n_angles);
    k_stats1<<<256, 128>>>(gn1_g, gn1_b);
    k_angle_scatter<<<4096, 128>>>(anb, ca, W_mask, n_angles);
    k_edge_stats<<<(n_edges + 127) / 128, 64>>>(ce, n_edges);
    k_stats2<<<256, 64>>>(gn2_g, gn2_b);
    k_final<<<2048, 256>>>(nbr, ce, W1a, b1a, W2a, b2a, W1b, b1b, W2b, b2b, out, n_edges);
}

// round 2
// speedup vs baseline: 1.1457x; 1.1457x over previous
#include <cuda_runtime.h>
#include <math.h>

#define NE_MAX 200000
#define NA_MAX 1600000

// ---- static scratch ----
__device__ float g_P0[(size_t)NE_MAX * 128];
__device__ float g_P1[(size_t)NE_MAX * 128];
__device__ float g_gbuf[(size_t)NA_MAX * 128];
__device__ float g_csum[256 * 128];
__device__ float g_csumsq[256 * 128];
__device__ unsigned g_ccnt[256];
__device__ float g_a1[256 * 128];
__device__ float g_b1[256 * 128];
__device__ float g_summed[(size_t)NE_MAX * 64];   // normalized v (post norm2-input)
__device__ unsigned g_acnt[NE_MAX];
__device__ unsigned g_off[NE_MAX + 1];
__device__ unsigned g_curs[NE_MAX];
__device__ int g_bucket[NA_MAX];
__device__ float g_esum[256 * 64];
__device__ float g_esumsq[256 * 64];
__device__ unsigned g_ecnt[256];
__device__ float g_a2[256 * 64];
__device__ float g_b2[256 * 64];

typedef unsigned long long ull;
__device__ __forceinline__ ull ffma2(ull a, ull b, ull c) {
    ull d; asm("fma.rn.f32x2 %0, %1, %2, %3;" : "=l"(d) : "l"(a), "l"(b), "l"(c)); return d;
}
__device__ __forceinline__ ull pack2(float x, float y) {
    ull d; asm("mov.b64 %0, {%1, %2};" : "=l"(d) : "f"(x), "f"(y)); return d;
}
__device__ __forceinline__ float2 unpack2(ull a) {
    float x, y; asm("mov.b64 {%0, %1}, %2;" : "=f"(x), "=f"(y) : "l"(a));
    return make_float2(x, y);
}

// ---- K0: zero accumulators ----
__global__ void k_zero(int n_edges) {
    int i = blockIdx.x * blockDim.x + threadIdx.x;
    int stride = gridDim.x * blockDim.x;
    for (int k = i; k < n_edges; k += stride) g_acnt[k] = 0u;
    for (int k = i; k < 256 * 128; k += stride) { g_csum[k] = 0.f; g_csumsq[k] = 0.f; }
    for (int k = i; k < 256 * 64; k += stride) { g_esum[k] = 0.f; g_esumsq[k] = 0.f; }
    for (int k = i; k < 256; k += stride) { g_ccnt[k] = 0u; g_ecnt[k] = 0u; }
}

// ---- K1: P0/P1 = nbr_fea @ W_full halves ----
__global__ void k_precompute(const float* __restrict__ nbr,
                             const float* __restrict__ W_full, int n_edges) {
    int j = threadIdx.x;          // 0..127
    int half = blockIdx.y;
    float w[64];
    const float* wb = W_full + (size_t)(40 + half * 64) * 128 + j;
#pragma unroll
    for (int k = 0; k < 64; k++) w[k] = wb[(size_t)k * 128];
    float* P = half ? g_P1 : g_P0;
    __shared__ float4 snb[16];
    for (int e = blockIdx.x; e < n_edges; e += gridDim.x) {
        if (j < 16) snb[j] = ((const float4*)(nbr + (size_t)e * 64))[j];
        __syncthreads();
        float acc = 0.f;
#pragma unroll
        for (int k = 0; k < 16; k++) {
            float4 v = snb[k];
            acc += v.x * w[4 * k] + v.y * w[4 * k + 1] + v.z * w[4 * k + 2] + v.w * w[4 * k + 3];
        }
        P[(size_t)e * 128 + j] = acc;
        __syncthreads();
    }
}

// ---- K2: count angles per src edge ----
__global__ void k_count(const int* __restrict__ anb, int n_angles) {
    int i = blockIdx.x * blockDim.x + threadIdx.x;
    if (i < n_angles) atomicAdd(&g_acnt[anb[2 * (size_t)i]], 1u);
}

// ---- K3: angle GEMM + crystal stats. Warp handles (channel-half, angle chunk). ----
__global__ void __launch_bounds__(256) k_angle_main(
        const float* __restrict__ af, const int* __restrict__ anb,
        const int* __restrict__ ca, const float* __restrict__ W,
        int n_angles, int warps_per_half) {
    int gw = blockIdx.x * (blockDim.x >> 5) + (threadIdx.x >> 5);
    int lane = threadIdx.x & 31;
    int half = (gw >= warps_per_half) ? 1 : 0;
    int w = half ? gw - warps_per_half : gw;
    int chunk = (n_angles + warps_per_half - 1) / warps_per_half;
    int a0 = w * chunk, aend = min(a0 + chunk, n_angles);
    if (a0 >= aend) return;
    int ch = half * 64 + 2 * lane;

    ull w2a[20], w2b[20];   // K-packed weights for the lane's 2 channels
#pragma unroll
    for (int kk = 0; kk < 20; kk++) {
        w2a[kk] = pack2(W[(size_t)(2 * kk) * 128 + ch],     W[(size_t)(2 * kk + 1) * 128 + ch]);
        w2b[kk] = pack2(W[(size_t)(2 * kk) * 128 + ch + 1], W[(size_t)(2 * kk + 1) * 128 + ch + 1]);
    }

    float lsum0 = 0.f, lsum1 = 0.f, lsq0 = 0.f, lsq1 = 0.f;
    int lcnt = 0;
    int curc = __ldg(&ca[a0]);
    for (int a = a0; a < aend; a++) {
        int c = __ldg(&ca[a]);
        if (c != curc) {
            atomicAdd(&g_csum[curc * 128 + ch], lsum0);
            atomicAdd(&g_csum[curc * 128 + ch + 1], lsum1);
            atomicAdd(&g_csumsq[curc * 128 + ch], lsq0);
            atomicAdd(&g_csumsq[curc * 128 + ch + 1], lsq1);
            if (half == 0 && lane == 0) atomicAdd(&g_ccnt[curc], (unsigned)lcnt);
            lsum0 = lsum1 = lsq0 = lsq1 = 0.f; lcnt = 0; curc = c;
        }
        int i0 = __ldg(&anb[2 * (size_t)a]);
        int i1 = __ldg(&anb[2 * (size_t)a + 1]);
        float2 p0 = *(const float2*)&g_P0[(size_t)i0 * 128 + ch];
        float2 p1 = *(const float2*)&g_P1[(size_t)i1 * 128 + ch];
        ull myaf = 0ull;
        if (lane < 20) myaf = *(const ull*)&af[(size_t)a * 40 + 2 * lane];
        ull acc0 = 0ull, acc1 = 0ull;
#pragma unroll
        for (int kk = 0; kk < 20; kk++) {
            ull afk = __shfl_sync(0xffffffffu, myaf, kk);
            acc0 = ffma2(afk, w2a[kk], acc0);
            acc1 = ffma2(afk, w2b[kk], acc1);
        }
        float2 u0 = unpack2(acc0), u1 = unpack2(acc1);
        float x0 = p0.x + p1.x + u0.x + u0.y;
        float x1 = p0.y + p1.y + u1.x + u1.y;
        *(float2*)&g_gbuf[(size_t)a * 128 + ch] = make_float2(x0, x1);
        lsum0 += x0; lsum1 += x1; lsq0 += x0 * x0; lsq1 += x1 * x1; lcnt++;
    }
    atomicAdd(&g_csum[curc * 128 + ch], lsum0);
    atomicAdd(&g_csum[curc * 128 + ch + 1], lsum1);
    atomicAdd(&g_csumsq[curc * 128 + ch], lsq0);
    atomicAdd(&g_csumsq[curc * 128 + ch + 1], lsq1);
    if (half == 0 && lane == 0) atomicAdd(&g_ccnt[curc], (unsigned)lcnt);
}

// ---- K4: finalize crystal_norm1 affine ----
__global__ void k_stats1(const float* __restrict__ gn1_g, const float* __restrict__ gn1_b) {
    int c = blockIdx.x, j = threadIdx.x;
    float cnt = fmaxf((float)g_ccnt[c], 1.f);
    float mean = g_csum[c * 128 + j] / cnt;
    float var = fmaxf(g_csumsq[c * 128 + j] / cnt - mean * mean, 0.f);
    float inv = rsqrtf(var + 1e-5f);
    float a = gn1_g[j] * inv;
    g_a1[c * 128 + j] = a;
    g_b1[c * 128 + j] = gn1_b[j] - mean * a;
}

// ---- K5: exclusive scan over counts -> offsets + cursors (single block) ----
__global__ void k_scan(int n_edges) {
    __shared__ unsigned ssum[1024];
    int t = threadIdx.x;
    int per = (n_edges + 1023) >> 10;
    int s = t * per, e = min(s + per, n_edges);
    unsigned local = 0;
    for (int i = s; i < e; i++) local += g_acnt[i];
    ssum[t] = local;
    __syncthreads();
    for (int off = 1; off < 1024; off <<= 1) {
        unsigned v = 0;
        if (t >= off) v = ssum[t - off];
        __syncthreads();
        if (t >= off) ssum[t] += v;
        __syncthreads();
    }
    unsigned run = (t > 0) ? ssum[t - 1] : 0u;
    for (int i = s; i < e; i++) {
        unsigned c = g_acnt[i];
        g_off[i] = run;
        g_curs[i] = run;
        run += c;
    }
    if (t == 1023) g_off[n_edges] = ssum[1023];
}

// ---- K6: fill CSR buckets ----
__global__ void k_fill(const int* __restrict__ anb, int n_angles) {
    int i = blockIdx.x * blockDim.x + threadIdx.x;
    if (i < n_angles) {
        int s = anb[2 * (size_t)i];
        unsigned p = atomicAdd(&g_curs[s], 1u);
        g_bucket[p] = i;
    }
}

// ---- K7: per-edge gather: norm1-apply, gate, sum, divide, edge-crystal stats ----
__global__ void __launch_bounds__(256) k_gather(
        const int* __restrict__ ca, const int* __restrict__ ce,
        const float* __restrict__ W_mask, int n_edges) {
    int gw = blockIdx.x * (blockDim.x >> 5) + (threadIdx.x >> 5);
    int lane = threadIdx.x & 31;
    int totalw = gridDim.x * (blockDim.x >> 5);
    int chunk = (n_edges + totalw - 1) / totalw;
    int e0 = gw * chunk, eend = min(e0 + chunk, n_edges);
    if (e0 >= eend) return;
    float4 wm = make_float4(0.f, 0.f, 0.f, 0.f);
    if (lane >= 16) wm = ((const float4*)W_mask)[lane - 16];
    float4 lsum = make_float4(0.f, 0.f, 0.f, 0.f);
    float4 lsq  = make_float4(0.f, 0.f, 0.f, 0.f);
    int lcnt = 0;
    int curc = __ldg(&ce[e0]);
    for (int e = e0; e < eend; e++) {
        int c = __ldg(&ce[e]);
        if (c != curc) {
            if (lane < 16) {
                int b = curc * 64 + 4 * lane;
                atomicAdd(&g_esum[b + 0], lsum.x); atomicAdd(&g_esum[b + 1], lsum.y);
                atomicAdd(&g_esum[b + 2], lsum.z); atomicAdd(&g_esum[b + 3], lsum.w);
                atomicAdd(&g_esumsq[b + 0], lsq.x); atomicAdd(&g_esumsq[b + 1], lsq.y);
                atomicAdd(&g_esumsq[b + 2], lsq.z); atomicAdd(&g_esumsq[b + 3], lsq.w);
            }
            if (lane == 0) atomicAdd(&g_ecnt[curc], (unsigned)lcnt);
            lsum = make_float4(0.f, 0.f, 0.f, 0.f);
            lsq = make_float4(0.f, 0.f, 0.f, 0.f);
            lcnt = 0; curc = c;
        }
        unsigned s = g_off[e], t = g_off[e + 1];
        float4 acc = make_float4(0.f, 0.f, 0.f, 0.f);
        if (s < t) {
            int aid = g_bucket[s];
            for (unsigned p = s; p < t; p++) {
                int aidn = (p + 1 < t) ? g_bucket[p + 1] : aid;   // prefetch
                int cc = __ldg(&ca[aid]);
                float4 g4 = *(const float4*)&g_gbuf[(size_t)aid * 128 + 4 * lane];
                float4 a4 = *(const float4*)&g_a1[cc * 128 + 4 * lane];
                float4 b4 = *(const float4*)&g_b1[cc * 128 + 4 * lane];
                float x0 = fmaf(g4.x, a4.x, b4.x);
                float x1 = fmaf(g4.y, a4.y, b4.y);
                float x2 = fmaf(g4.z, a4.z, b4.z);
                float x3 = fmaf(g4.w, a4.w, b4.w);
                float part = x0 * wm.x + x1 * wm.y + x2 * wm.z + x3 * wm.w;
#pragma unroll
                for (int o = 16; o; o >>= 1) part += __shfl_xor_sync(0xffffffffu, part, o);
                float ex = __expf(2.f * part);
                float filt = 1.f - 2.f / (ex + 1.f);   // tanh
                acc.x += filt * fmaxf(x0, 0.f);
                acc.y += filt * fmaxf(x1, 0.f);
                acc.z += filt * fmaxf(x2, 0.f);
                acc.w += filt * fmaxf(x3, 0.f);
                aid = aidn;
            }
        }
        float inv = 1.f / fmaxf((float)(t - s), 1.f);
        float4 v = make_float4(acc.x * inv, acc.y * inv, acc.z * inv, acc.w * inv);
        if (lane < 16) {
            *(float4*)&g_summed[(size_t)e * 64 + 4 * lane] = v;
            lsum.x += v.x; lsum.y += v.y; lsum.z += v.z; lsum.w += v.w;
            lsq.x += v.x * v.x; lsq.y += v.y * v.y; lsq.z += v.z * v.z; lsq.w += v.w * v.w;
        }
        lcnt++;
    }
    if (lane < 16) {
        int b = curc * 64 + 4 * lane;
        atomicAdd(&g_esum[b + 0], lsum.x); atomicAdd(&g_esum[b + 1], lsum.y);
        atomicAdd(&g_esum[b + 2], lsum.z); atomicAdd(&g_esum[b + 3], lsum.w);
        atomicAdd(&g_esumsq[b + 0], lsq.x); atomicAdd(&g_esumsq[b + 1], lsq.y);
        atomicAdd(&g_esumsq[b + 2], lsq.z); atomicAdd(&g_esumsq[b + 3], lsq.w);
    }
    if (lane == 0) atomicAdd(&g_ecnt[curc], (unsigned)lcnt);
}

// ---- K8: finalize crystal_norm2 affine ----
__global__ void k_stats2(const float* __restrict__ gn2_g, const float* __restrict__ gn2_b) {
    int c = blockIdx.x, j = threadIdx.x;
    float cnt = fmaxf((float)g_ecnt[c], 1.f);
    float mean = g_esum[c * 64 + j] / cnt;
    float var = fmaxf(g_esumsq[c * 64 + j] / cnt - mean * mean, 0.f);
    float inv = rsqrtf(var + 1e-5f);
    float a = gn2_g[j] * inv;
    g_a2[c * 64 + j] = a;
    g_b2[c * 64 + j] = gn2_b[j] - mean * a;
}

// ---- K9: normalize edges, two residual MLPs, final relu ----
__global__ void k_final(const float* __restrict__ nbr, const int* __restrict__ ce,
                        const float* __restrict__ W1a, const float* __restrict__ b1a,
                        const float* __restrict__ W2a, const float* __restrict__ b2a,
                        const float* __restrict__ W1b, const float* __restrict__ b1b,
                        const float* __restrict__ W2b, const float* __restrict__ b2b,
                        float* __restrict__ out, int n_edges) {
    __shared__ float sW1a[64 * 32], sW2a[32 * 64], sW1b[64 * 32], sW2b[32 * 64];
    __shared__ float sb1a[32], sb2a[64], sb1b[32], sb2b[64];
    __shared__ float sh_h[4][64];
    __shared__ float sh_r[4][32];
    int t = threadIdx.x;  // 256
    for (int k = t; k < 2048; k += 256) {
        sW1a[k] = W1a[k]; sW2a[k] = W2a[k]; sW1b[k] = W1b[k]; sW2b[k] = W2b[k];
    }
    if (t < 32) { sb1a[t] = b1a[t]; sb1b[t] = b1b[t]; }
    if (t < 64) { sb2a[t] = b2a[t]; sb2b[t] = b2b[t]; }
    __syncthreads();
    int g = t >> 6, j = t & 63;
    int total = (n_edges + 3) >> 2;
    for (int blk = blockIdx.x; blk < total; blk += gridDim.x) {
        int e = blk * 4 + g;
        bool valid = e < n_edges;
        float h = 0.f;
        if (valid) {
            int c = ce[e];
            h = g_summed[(size_t)e * 64 + j] * g_a2[c * 64 + j] + g_b2[c * 64 + j];
        }
        sh_h[g][j] = h;
        __syncthreads();
        if (j < 32) {
            float acc = sb1a[j];
#pragma unroll
            for (int k = 0; k < 64; k++) acc += sh_h[g][k] * sW1a[k * 32 + j];
            sh_r[g][j] = fmaxf(acc, 0.f);
        }
        __syncthreads();
        {
            float acc = sb2a[j];
#pragma unroll
            for (int m = 0; m < 32; m++) acc += sh_r[g][m] * sW2a[m * 64 + j];
            h += acc;
            sh_h[g][j] = h;
        }
        __syncthreads();
        if (j < 32) {
            float acc = sb1b[j];
#pragma unroll
            for (int k = 0; k < 64; k++) acc += sh_h[g][k] * sW1b[k * 32 + j];
            sh_r[g][j] = fmaxf(acc, 0.f);
        }
        __syncthreads();
        {
            float acc = sb2b[j];
#pragma unroll
            for (int m = 0; m < 32; m++) acc += sh_r[g][m] * sW2b[m * 64 + j];
            h += acc;
        }
        if (valid)
            out[(size_t)e * 64 + j] =
                0.7071067811865476f * fmaxf(nbr[(size_t)e * 64 + j] + h, 0.f);
        __syncthreads();
    }
}

extern "C" void kernel_launch(void* const* d_in, const int* in_sizes, int n_in,
                              void* d_out, int out_size) {
    const float* nbr       = (const float*)d_in[0];
    const float* angle_fea = (const float*)d_in[1];
    const int*   anb       = (const int*)d_in[2];
    const int*   ce        = (const int*)d_in[3];
    const int*   ca        = (const int*)d_in[4];
    const float* W_full    = (const float*)d_in[5];
    const float* W_mask    = (const float*)d_in[6];
    const float* gn1_g     = (const float*)d_in[7];
    const float* gn1_b     = (const float*)d_in[8];
    const float* gn2_g     = (const float*)d_in[9];
    const float* gn2_b     = (const float*)d_in[10];
    const float* W1a       = (const float*)d_in[11];
    const float* b1a       = (const float*)d_in[12];
    const float* W2a       = (const float*)d_in[13];
    const float* b2a       = (const float*)d_in[14];
    const float* W1b       = (const float*)d_in[15];
    const float* b1b       = (const float*)d_in[16];
    const float* W2b       = (const float*)d_in[17];
    const float* b2b       = (const float*)d_in[18];
    float* out = (float*)d_out;

    int n_edges  = in_sizes[0] / 64;
    int n_angles = in_sizes[1] / 40;

    k_zero<<<1024, 256>>>(n_edges);
    dim3 g1(1024, 2);
    k_precompute<<<g1, 128>>>(nbr, W_full, n_edges);
    k_count<<<(n_angles + 255) / 256, 256>>>(anb, n_angles);
    const int WARPS_PER_HALF = 8192;  // 2048 blocks * 8 warps / 2 halves
    k_angle_main<<<2048, 256>>>(angle_fea, anb, ca, W_full, n_angles, WARPS_PER_HALF);
    k_stats1<<<256, 128>>>(gn1_g, gn1_b);
    k_scan<<<1, 1024>>>(n_edges);
    k_fill<<<(n_angles + 255) / 256, 256>>>(anb, n_angles);
    k_gather<<<1024, 256>>>(ca, ce, W_mask, n_edges);
    k_stats2<<<256, 64>>>(gn2_g, gn2_b);
    k_final<<<2048, 256>>>(nbr, ce, W1a, b1a, W2a, b2a, W1b, b1b, W2b, b2b, out, n_edges);
}

// round 3
// speedup vs baseline: 1.2967x; 1.1318x over previous
#include <cuda_runtime.h>
#include <math.h>

#define NE_MAX 200000
#define NA_MAX 1600000

// ---- static scratch ----
__device__ float g_P0[(size_t)NE_MAX * 128];
__device__ float g_P1[(size_t)NE_MAX * 128];
__device__ float g_gbuf[(size_t)NA_MAX * 128];
__device__ float g_y[(size_t)NA_MAX * 64];        // filt * relu(core)
__device__ float g_csum[256 * 128];
__device__ float g_csumsq[256 * 128];
__device__ unsigned g_ccnt[256];
__device__ float g_a1[256 * 128];
__device__ float g_b1[256 * 128];
__device__ float g_summed[(size_t)NE_MAX * 64];
__device__ unsigned g_acnt[NE_MAX];
__device__ unsigned g_off[NE_MAX + 1];
__device__ unsigned g_curs[NE_MAX];
__device__ int g_bucket[NA_MAX];
__device__ float g_esum[256 * 64];
__device__ float g_esumsq[256 * 64];
__device__ unsigned g_ecnt[256];
__device__ float g_a2[256 * 64];
__device__ float g_b2[256 * 64];

typedef unsigned long long ull;
__device__ __forceinline__ ull ffma2(ull a, ull b, ull c) {
    ull d; asm("fma.rn.f32x2 %0, %1, %2, %3;" : "=l"(d) : "l"(a), "l"(b), "l"(c)); return d;
}
__device__ __forceinline__ ull pack2(float x, float y) {
    ull d; asm("mov.b64 %0, {%1, %2};" : "=l"(d) : "f"(x), "f"(y)); return d;
}
__device__ __forceinline__ float2 unpack2(ull a) {
    float x, y; asm("mov.b64 {%0, %1}, %2;" : "=f"(x), "=f"(y) : "l"(a));
    return make_float2(x, y);
}

// ---- K0: zero accumulators ----
__global__ void k_zero(int n_edges) {
    int i = blockIdx.x * blockDim.x + threadIdx.x;
    int stride = gridDim.x * blockDim.x;
    for (int k = i; k < n_edges; k += stride) g_acnt[k] = 0u;
    for (int k = i; k < 256 * 128; k += stride) { g_csum[k] = 0.f; g_csumsq[k] = 0.f; }
    for (int k = i; k < 256 * 64; k += stride) { g_esum[k] = 0.f; g_esumsq[k] = 0.f; }
    for (int k = i; k < 256; k += stride) { g_ccnt[k] = 0u; g_ecnt[k] = 0u; }
}

// ---- K1: P0/P1 = nbr_fea @ W_full halves ----
__global__ void k_precompute(const float* __restrict__ nbr,
                             const float* __restrict__ W_full, int n_edges) {
    int j = threadIdx.x;          // 0..127
    int half = blockIdx.y;
    float w[64];
    const float* wb = W_full + (size_t)(40 + half * 64) * 128 + j;
#pragma unroll
    for (int k = 0; k < 64; k++) w[k] = wb[(size_t)k * 128];
    float* P = half ? g_P1 : g_P0;
    __shared__ float4 snb[2][16];
    int nb = gridDim.x;
    for (int e2 = blockIdx.x * 2; e2 < n_edges; e2 += nb * 2) {
        int g = j >> 6, jj = j & 63;   // two edges per round
        int e = e2 + g;
        if (jj < 16 && e < n_edges) snb[g][jj] = ((const float4*)(nbr + (size_t)e * 64))[jj];
        __syncthreads();
#pragma unroll 2
        for (int gg = 0; gg < 2; gg++) {
            int ee = e2 + gg;
            if (ee >= n_edges) break;
            float acc = 0.f;
#pragma unroll
            for (int k = 0; k < 16; k++) {
                float4 v = snb[gg][k];
                acc += v.x * w[4 * k] + v.y * w[4 * k + 1] + v.z * w[4 * k + 2] + v.w * w[4 * k + 3];
            }
            P[(size_t)ee * 128 + j] = acc;
        }
        __syncthreads();
    }
}

// ---- K2: count angles per src edge ----
__global__ void k_count(const int* __restrict__ anb, int n_angles) {
    int i = blockIdx.x * blockDim.x + threadIdx.x;
    if (i < n_angles) atomicAdd(&g_acnt[anb[2 * (size_t)i]], 1u);
}

// ---- K3: angle GEMM + crystal stats. Block(128)=4 warps cover 128ch; batch-4 pipeline ----
__global__ void __launch_bounds__(128) k_angle_main(
        const float* __restrict__ af, const int* __restrict__ anb,
        const int* __restrict__ ca, const float* __restrict__ W, int n_angles) {
    int lane = threadIdx.x & 31;
    int ch = threadIdx.x;   // 0..127 (warp w covers [32w,32w+32))

    ull w2[20];   // k-pair packed weights for this channel
#pragma unroll
    for (int kk = 0; kk < 20; kk++)
        w2[kk] = pack2(W[(size_t)(2 * kk) * 128 + ch], W[(size_t)(2 * kk + 1) * 128 + ch]);

    int chunk = (n_angles + gridDim.x - 1) / gridDim.x;
    int a0 = blockIdx.x * chunk, aend = min(a0 + chunk, n_angles);
    if (a0 >= aend) return;

    float lsum = 0.f, lsq = 0.f;
    int lcnt = 0;
    int curc = __ldg(&ca[a0]);
    for (int base = a0; base < aend; base += 4) {
        int nb = aend - base;   // >=1
        int i0[4], i1[4], cc[4];
        ull afv[4];
#pragma unroll
        for (int t = 0; t < 4; t++) {
            int aa = base + ((t < nb) ? t : 0);
            i0[t] = __ldg(&anb[2 * (size_t)aa]);
            i1[t] = __ldg(&anb[2 * (size_t)aa + 1]);
            cc[t] = __ldg(&ca[aa]);
        }
#pragma unroll
        for (int t = 0; t < 4; t++) {
            int aa = base + ((t < nb) ? t : 0);
            afv[t] = (lane < 20) ? *(const ull*)&af[(size_t)aa * 40 + 2 * lane] : 0ull;
        }
        float p0[4], p1[4];
#pragma unroll
        for (int t = 0; t < 4; t++) {
            p0[t] = __ldg(&g_P0[(size_t)i0[t] * 128 + ch]);
            p1[t] = __ldg(&g_P1[(size_t)i1[t] * 128 + ch]);
        }
#pragma unroll
        for (int t = 0; t < 4; t++) {
            if (t >= nb) break;
            if (cc[t] != curc) {
                atomicAdd(&g_csum[curc * 128 + ch], lsum);
                atomicAdd(&g_csumsq[curc * 128 + ch], lsq);
                if (ch == 0) atomicAdd(&g_ccnt[curc], (unsigned)lcnt);
                lsum = 0.f; lsq = 0.f; lcnt = 0; curc = cc[t];
            }
            ull acc = 0ull;
#pragma unroll
            for (int kk = 0; kk < 20; kk++) {
                ull afk = __shfl_sync(0xffffffffu, afv[t], kk);
                acc = ffma2(afk, w2[kk], acc);
            }
            float2 u = unpack2(acc);
            float x = u.x + u.y + p0[t] + p1[t];
            g_gbuf[(size_t)(base + t) * 128 + ch] = x;
            lsum += x; lsq += x * x; lcnt++;
        }
    }
    atomicAdd(&g_csum[curc * 128 + ch], lsum);
    atomicAdd(&g_csumsq[curc * 128 + ch], lsq);
    if (ch == 0) atomicAdd(&g_ccnt[curc], (unsigned)lcnt);
}

// ---- K4: finalize crystal_norm1 affine ----
__global__ void k_stats1(const float* __restrict__ gn1_g, const float* __restrict__ gn1_b) {
    int c = blockIdx.x, j = threadIdx.x;
    float cnt = fmaxf((float)g_ccnt[c], 1.f);
    float mean = g_csum[c * 128 + j] / cnt;
    float var = fmaxf(g_csumsq[c * 128 + j] / cnt - mean * mean, 0.f);
    float inv = rsqrtf(var + 1e-5f);
    float a = gn1_g[j] * inv;
    g_a1[c * 128 + j] = a;
    g_b1[c * 128 + j] = gn1_b[j] - mean * a;
}

// ---- K5: exclusive scan over counts -> offsets + cursors (single block) ----
__global__ void k_scan(int n_edges) {
    __shared__ unsigned ssum[1024];
    int t = threadIdx.x;
    int per = (n_edges + 1023) >> 10;
    int s = t * per, e = min(s + per, n_edges);
    unsigned local = 0;
    for (int i = s; i < e; i++) local += g_acnt[i];
    ssum[t] = local;
    __syncthreads();
    for (int off = 1; off < 1024; off <<= 1) {
        unsigned v = 0;
        if (t >= off) v = ssum[t - off];
        __syncthreads();
        if (t >= off) ssum[t] += v;
        __syncthreads();
    }
    unsigned run = (t > 0) ? ssum[t - 1] : 0u;
    for (int i = s; i < e; i++) {
        unsigned c = g_acnt[i];
        g_off[i] = run;
        g_curs[i] = run;
        run += c;
    }
    if (t == 1023) g_off[n_edges] = ssum[1023];
}

// ---- K6: fill CSR buckets ----
__global__ void k_fill(const int* __restrict__ anb, int n_angles) {
    int i = blockIdx.x * blockDim.x + threadIdx.x;
    if (i < n_angles) {
        int s = anb[2 * (size_t)i];
        unsigned p = atomicAdd(&g_curs[s], 1u);
        g_bucket[p] = i;
    }
}

// ---- K7: streaming gate: y = filt * relu(norm1(gated)) ----
__global__ void __launch_bounds__(256) k_gate(const int* __restrict__ ca,
                                              const float* __restrict__ W_mask,
                                              int n_angles) {
    int gw = blockIdx.x * (blockDim.x >> 5) + (threadIdx.x >> 5);
    int lane = threadIdx.x & 31;
    int totalw = gridDim.x * (blockDim.x >> 5);
    int chunk = (n_angles + totalw - 1) / totalw;
    int a0 = gw * chunk, aend = min(a0 + chunk, n_angles);
    if (a0 >= aend) return;
    float4 wm = make_float4(0.f, 0.f, 0.f, 0.f);
    if (lane >= 16) wm = ((const float4*)W_mask)[lane - 16];
    int curc = -1;
    float4 av, bv;
    for (int a = a0; a < aend; a++) {
        int c = __ldg(&ca[a]);
        if (c != curc) {
            curc = c;
            av = *(const float4*)&g_a1[c * 128 + 4 * lane];
            bv = *(const float4*)&g_b1[c * 128 + 4 * lane];
        }
        float4 g4 = *(const float4*)&g_gbuf[(size_t)a * 128 + 4 * lane];
        float x0 = fmaf(g4.x, av.x, bv.x);
        float x1 = fmaf(g4.y, av.y, bv.y);
        float x2 = fmaf(g4.z, av.z, bv.z);
        float x3 = fmaf(g4.w, av.w, bv.w);
        float part = x0 * wm.x + x1 * wm.y + x2 * wm.z + x3 * wm.w;
#pragma unroll
        for (int o = 16; o; o >>= 1) part += __shfl_xor_sync(0xffffffffu, part, o);
        float ex = __expf(2.f * part);
        float filt = 1.f - 2.f / (ex + 1.f);   // tanh
        if (lane < 16) {
            float4 y;
            y.x = filt * fmaxf(x0, 0.f);
            y.y = filt * fmaxf(x1, 0.f);
            y.z = filt * fmaxf(x2, 0.f);
            y.w = filt * fmaxf(x3, 0.f);
            *(float4*)&g_y[(size_t)a * 64 + 4 * lane] = y;
        }
    }
}

// ---- K8: per-edge segment-sum of y + norm2 stats (ce sorted) ----
__global__ void __launch_bounds__(256) k_gather(const int* __restrict__ ce, int n_edges) {
    int gw = blockIdx.x * (blockDim.x >> 5) + (threadIdx.x >> 5);
    int lane = threadIdx.x & 31;
    int totalw = gridDim.x * (blockDim.x >> 5);
    int chunk = (n_edges + totalw - 1) / totalw;
    int e0 = gw * chunk, eend = min(e0 + chunk, n_edges);
    if (e0 >= eend) return;
    float2 lsum = make_float2(0.f, 0.f), lsq = make_float2(0.f, 0.f);
    int lcnt = 0;
    int curc = __ldg(&ce[e0]);
    for (int e = e0; e < eend; e++) {
        int c = __ldg(&ce[e]);
        if (c != curc) {
            int b = curc * 64 + 2 * lane;
            atomicAdd(&g_esum[b], lsum.x); atomicAdd(&g_esum[b + 1], lsum.y);
            atomicAdd(&g_esumsq[b], lsq.x); atomicAdd(&g_esumsq[b + 1], lsq.y);
            if (lane == 0) atomicAdd(&g_ecnt[curc], (unsigned)lcnt);
            lsum = make_float2(0.f, 0.f); lsq = make_float2(0.f, 0.f);
            lcnt = 0; curc = c;
        }
        unsigned s = g_off[e], t = g_off[e + 1];
        float2 acc = make_float2(0.f, 0.f);
        unsigned p = s;
        // unroll by 2 for MLP
        for (; p + 2 <= t; p += 2) {
            int a0i = __ldg(&g_bucket[p]);
            int a1i = __ldg(&g_bucket[p + 1]);
            float2 y0 = *(const float2*)&g_y[(size_t)a0i * 64 + 2 * lane];
            float2 y1 = *(const float2*)&g_y[(size_t)a1i * 64 + 2 * lane];
            acc.x += y0.x + y1.x;
            acc.y += y0.y + y1.y;
        }
        if (p < t) {
            int a0i = __ldg(&g_bucket[p]);
            float2 y0 = *(const float2*)&g_y[(size_t)a0i * 64 + 2 * lane];
            acc.x += y0.x; acc.y += y0.y;
        }
        float inv = 1.f / fmaxf((float)(t - s), 1.f);
        float2 v = make_float2(acc.x * inv, acc.y * inv);
        *(float2*)&g_summed[(size_t)e * 64 + 2 * lane] = v;
        lsum.x += v.x; lsum.y += v.y;
        lsq.x += v.x * v.x; lsq.y += v.y * v.y;
        lcnt++;
    }
    int b = curc * 64 + 2 * lane;
    atomicAdd(&g_esum[b], lsum.x); atomicAdd(&g_esum[b + 1], lsum.y);
    atomicAdd(&g_esumsq[b], lsq.x); atomicAdd(&g_esumsq[b + 1], lsq.y);
    if (lane == 0) atomicAdd(&g_ecnt[curc], (unsigned)lcnt);
}

// ---- K9: finalize crystal_norm2 affine ----
__global__ void k_stats2(const float* __restrict__ gn2_g, const float* __restrict__ gn2_b) {
    int c = blockIdx.x, j = threadIdx.x;
    float cnt = fmaxf((float)g_ecnt[c], 1.f);
    float mean = g_esum[c * 64 + j] / cnt;
    float var = fmaxf(g_esumsq[c * 64 + j] / cnt - mean * mean, 0.f);
    float inv = rsqrtf(var + 1e-5f);
    float a = gn2_g[j] * inv;
    g_a2[c * 64 + j] = a;
    g_b2[c * 64 + j] = gn2_b[j] - mean * a;
}

// ---- K10: thread-per-edge residual MLPs, weights via uniform shared broadcasts ----
__global__ void __launch_bounds__(256) k_final(
        const float* __restrict__ nbr, const int* __restrict__ ce,
        const float* __restrict__ W1a, const float* __restrict__ b1a,
        const float* __restrict__ W2a, const float* __restrict__ b2a,
        const float* __restrict__ W1b, const float* __restrict__ b1b,
        const float* __restrict__ W2b, const float* __restrict__ b2b,
        float* __restrict__ out, int n_edges) {
    __shared__ float4 sW1a[512], sW2a[512], sW1b[512], sW2b[512];
    __shared__ float sb1a[32], sb2a[64], sb1b[32], sb2b[64];
    int t = threadIdx.x;
    for (int k = t; k < 512; k += 256) {
        sW1a[k] = ((const float4*)W1a)[k];
        sW2a[k] = ((const float4*)W2a)[k];
        sW1b[k] = ((const float4*)W1b)[k];
        sW2b[k] = ((const float4*)W2b)[k];
    }
    if (t < 32) { sb1a[t] = b1a[t]; sb1b[t] = b1b[t]; }
    if (t < 64) { sb2a[t] = b2a[t]; sb2b[t] = b2b[t]; }
    __syncthreads();
    int e = blockIdx.x * 256 + t;
    if (e >= n_edges) return;

    float h[64];
    int c = __ldg(&ce[e]);
    {
        const float4* s4 = (const float4*)&g_summed[(size_t)e * 64];
        const float4* a4 = (const float4*)&g_a2[c * 64];
        const float4* b4 = (const float4*)&g_b2[c * 64];
#pragma unroll
        for (int i = 0; i < 16; i++) {
            float4 sv = s4[i], av = a4[i], bv = b4[i];
            h[4 * i + 0] = fmaf(sv.x, av.x, bv.x);
            h[4 * i + 1] = fmaf(sv.y, av.y, bv.y);
            h[4 * i + 2] = fmaf(sv.z, av.z, bv.z);
            h[4 * i + 3] = fmaf(sv.w, av.w, bv.w);
        }
    }
    // ---- residual block A ----
    float r[32];
    {
        ull racc[16];
#pragma unroll
        for (int j = 0; j < 16; j++) racc[j] = pack2(sb1a[2 * j], sb1a[2 * j + 1]);
#pragma unroll
        for (int k = 0; k < 64; k++) {
            ull hk = pack2(h[k], h[k]);
#pragma unroll
            for (int j = 0; j < 8; j++) {
                float4 w4 = sW1a[k * 8 + j];
                racc[2 * j]     = ffma2(hk, pack2(w4.x, w4.y), racc[2 * j]);
                racc[2 * j + 1] = ffma2(hk, pack2(w4.z, w4.w), racc[2 * j + 1]);
            }
        }
#pragma unroll
        for (int j = 0; j < 16; j++) {
            float2 u = unpack2(racc[j]);
            r[2 * j] = fmaxf(u.x, 0.f);
            r[2 * j + 1] = fmaxf(u.y, 0.f);
        }
        ull hacc[32];
#pragma unroll
        for (int j = 0; j < 32; j++) hacc[j] = pack2(h[2 * j] + sb2a[2 * j], h[2 * j + 1] + sb2a[2 * j + 1]);
#pragma unroll
        for (int k = 0; k < 32; k++) {
            ull rk = pack2(r[k], r[k]);
#pragma unroll
            for (int j = 0; j < 16; j++) {
                float4 w4 = sW2a[k * 16 + j];
                hacc[2 * j]     = ffma2(rk, pack2(w4.x, w4.y), hacc[2 * j]);
                hacc[2 * j + 1] = ffma2(rk, pack2(w4.z, w4.w), hacc[2 * j + 1]);
            }
        }
#pragma unroll
        for (int j = 0; j < 32; j++) {
            float2 u = unpack2(hacc[j]);
            h[2 * j] = u.x; h[2 * j + 1] = u.y;
        }
    }
    // ---- residual block B ----
    {
        ull racc[16];
#pragma unroll
        for (int j = 0; j < 16; j++) racc[j] = pack2(sb1b[2 * j], sb1b[2 * j + 1]);
#pragma unroll
        for (int k = 0; k < 64; k++) {
            ull hk = pack2(h[k], h[k]);
#pragma unroll
            for (int j = 0; j < 8; j++) {
                float4 w4 = sW1b[k * 8 + j];
                racc[2 * j]     = ffma2(hk, pack2(w4.x, w4.y), racc[2 * j]);
                racc[2 * j + 1] = ffma2(hk, pack2(w4.z, w4.w), racc[2 * j + 1]);
            }
        }
#pragma unroll
        for (int j = 0; j < 16; j++) {
            float2 u = unpack2(racc[j]);
            r[2 * j] = fmaxf(u.x, 0.f);
            r[2 * j + 1] = fmaxf(u.y, 0.f);
        }
        ull hacc[32];
#pragma unroll
        for (int j = 0; j < 32; j++) hacc[j] = pack2(h[2 * j] + sb2b[2 * j], h[2 * j + 1] + sb2b[2 * j + 1]);
#pragma unroll
        for (int k = 0; k < 32; k++) {
            ull rk = pack2(r[k], r[k]);
#pragma unroll
            for (int j = 0; j < 16; j++) {
                float4 w4 = sW2b[k * 16 + j];
                hacc[2 * j]     = ffma2(rk, pack2(w4.x, w4.y), hacc[2 * j]);
                hacc[2 * j + 1] = ffma2(rk, pack2(w4.z, w4.w), hacc[2 * j + 1]);
            }
        }
#pragma unroll
        for (int j = 0; j < 32; j++) {
            float2 u = unpack2(hacc[j]);
            h[2 * j] = u.x; h[2 * j + 1] = u.y;
        }
    }
    // ---- output ----
    {
        const float4* n4 = (const float4*)&nbr[(size_t)e * 64];
        float4* o4 = (float4*)&out[(size_t)e * 64];
#pragma unroll
        for (int i = 0; i < 16; i++) {
            float4 nv = n4[i];
            float4 ov;
            ov.x = 0.7071067811865476f * fmaxf(nv.x + h[4 * i + 0], 0.f);
            ov.y = 0.7071067811865476f * fmaxf(nv.y + h[4 * i + 1], 0.f);
            ov.z = 0.7071067811865476f * fmaxf(nv.z + h[4 * i + 2], 0.f);
            ov.w = 0.7071067811865476f * fmaxf(nv.w + h[4 * i + 3], 0.f);
            o4[i] = ov;
        }
    }
}

extern "C" void kernel_launch(void* const* d_in, const int* in_sizes, int n_in,
                              void* d_out, int out_size) {
    const float* nbr       = (const float*)d_in[0];
    const float* angle_fea = (const float*)d_in[1];
    const int*   anb       = (const int*)d_in[2];
    const int*   ce        = (const int*)d_in[3];
    const int*   ca        = (const int*)d_in[4];
    const float* W_full    = (const float*)d_in[5];
    const float* W_mask    = (const float*)d_in[6];
    const float* gn1_g     = (const float*)d_in[7];
    const float* gn1_b     = (const float*)d_in[8];
    const float* gn2_g     = (const float*)d_in[9];
    const float* gn2_b     = (const float*)d_in[10];
    const float* W1a       = (const float*)d_in[11];
    const float* b1a       = (const float*)d_in[12];
    const float* W2a       = (const float*)d_in[13];
    const float* b2a       = (const float*)d_in[14];
    const float* W1b       = (const float*)d_in[15];
    const float* b1b       = (const float*)d_in[16];
    const float* W2b       = (const float*)d_in[17];
    const float* b2b       = (const float*)d_in[18];
    float* out = (float*)d_out;

    int n_edges  = in_sizes[0] / 64;
    int n_angles = in_sizes[1] / 40;

    k_zero<<<512, 256>>>(n_edges);
    dim3 g1(1024, 2);
    k_precompute<<<g1, 128>>>(nbr, W_full, n_edges);
    k_count<<<(n_angles + 255) / 256, 256>>>(anb, n_angles);
    k_angle_main<<<4096, 128>>>(angle_fea, anb, ca, W_full, n_angles);
    k_stats1<<<256, 128>>>(gn1_g, gn1_b);
    k_scan<<<1, 1024>>>(n_edges);
    k_fill<<<(n_angles + 255) / 256, 256>>>(anb, n_angles);
    k_gate<<<2048, 256>>>(ca, W_mask, n_angles);
    k_gather<<<1024, 256>>>(ce, n_edges);
    k_stats2<<<256, 64>>>(gn2_g, gn2_b);
    k_final<<<(n_edges + 255) / 256, 256>>>(nbr, ce, W1a, b1a, W2a, b2a,
                                            W1b, b1b, W2b, b2b, out, n_edges);
}

// round 4
// speedup vs baseline: 1.5791x; 1.2178x over previous
#include <cuda_runtime.h>
#include <cuda_fp16.h>
#include <math.h>

#define NE_MAX 200000
#define NA_MAX 1600000
#define ATILE 32

// ---- static scratch ----
__device__ float g_P0[(size_t)NE_MAX * 128];
__device__ float g_P1[(size_t)NE_MAX * 128];
__device__ __half g_gbufh[(size_t)NA_MAX * 128];
__device__ __half g_yh[(size_t)NA_MAX * 64];
__device__ float g_csum[256 * 128];
__device__ float g_csumsq[256 * 128];
__device__ unsigned g_ccnt[256];
__device__ float g_a1[256 * 128];
__device__ float g_b1[256 * 128];
__device__ float g_summed[(size_t)NE_MAX * 64];
__device__ unsigned g_acnt[NE_MAX];
__device__ unsigned g_off[NE_MAX + 1];
__device__ unsigned g_curs[NE_MAX];
__device__ int g_bucket[NA_MAX];
__device__ float g_esum[256 * 64];
__device__ float g_esumsq[256 * 64];
__device__ unsigned g_ecnt[256];
__device__ float g_a2[256 * 64];
__device__ float g_b2[256 * 64];

typedef unsigned long long ull;
__device__ __forceinline__ ull ffma2(ull a, ull b, ull c) {
    ull d; asm("fma.rn.f32x2 %0, %1, %2, %3;" : "=l"(d) : "l"(a), "l"(b), "l"(c)); return d;
}
__device__ __forceinline__ ull pack2(float x, float y) {
    ull d; asm("mov.b64 %0, {%1, %2};" : "=l"(d) : "f"(x), "f"(y)); return d;
}
__device__ __forceinline__ float2 unpack2(ull a) {
    float x, y; asm("mov.b64 {%0, %1}, %2;" : "=f"(x), "=f"(y) : "l"(a));
    return make_float2(x, y);
}
__device__ __forceinline__ float4 ld_half4(const __half* p) {
    uint2 u = *(const uint2*)p;
    float2 fa = __half22float2(*(__half2*)&u.x);
    float2 fb = __half22float2(*(__half2*)&u.y);
    return make_float4(fa.x, fa.y, fb.x, fb.y);
}
__device__ __forceinline__ void st_half4(__half* p, float4 v) {
    __half2 a = __floats2half2_rn(v.x, v.y);
    __half2 b = __floats2half2_rn(v.z, v.w);
    uint2 u; u.x = *(unsigned*)&a; u.y = *(unsigned*)&b;
    *(uint2*)p = u;
}

// ---- K0: zero accumulators ----
__global__ void k_zero(int n_edges) {
    int i = blockIdx.x * blockDim.x + threadIdx.x;
    int stride = gridDim.x * blockDim.x;
    for (int k = i; k < n_edges; k += stride) g_acnt[k] = 0u;
    for (int k = i; k < 256 * 128; k += stride) { g_csum[k] = 0.f; g_csumsq[k] = 0.f; }
    for (int k = i; k < 256 * 64; k += stride) { g_esum[k] = 0.f; g_esumsq[k] = 0.f; }
    for (int k = i; k < 256; k += stride) { g_ccnt[k] = 0u; g_ecnt[k] = 0u; }
}

// ---- K1: P0/P1 = nbr_fea @ W_full halves ----
__global__ void k_precompute(const float* __restrict__ nbr,
                             const float* __restrict__ W_full, int n_edges) {
    int j = threadIdx.x;          // 0..127
    int half = blockIdx.y;
    float w[64];
    const float* wb = W_full + (size_t)(40 + half * 64) * 128 + j;
#pragma unroll
    for (int k = 0; k < 64; k++) w[k] = wb[(size_t)k * 128];
    float* P = half ? g_P1 : g_P0;
    __shared__ float4 snb[2][16];
    int nb = gridDim.x;
    for (int e2 = blockIdx.x * 2; e2 < n_edges; e2 += nb * 2) {
        int g = j >> 6, jj = j & 63;
        int e = e2 + g;
        if (jj < 16 && e < n_edges) snb[g][jj] = ((const float4*)(nbr + (size_t)e * 64))[jj];
        __syncthreads();
#pragma unroll 2
        for (int gg = 0; gg < 2; gg++) {
            int ee = e2 + gg;
            if (ee >= n_edges) break;
            float acc = 0.f;
#pragma unroll
            for (int k = 0; k < 16; k++) {
                float4 v = snb[gg][k];
                acc += v.x * w[4 * k] + v.y * w[4 * k + 1] + v.z * w[4 * k + 2] + v.w * w[4 * k + 3];
            }
            P[(size_t)ee * 128 + j] = acc;
        }
        __syncthreads();
    }
}

// ---- K2: count angles per src edge ----
__global__ void k_count(const int* __restrict__ anb, int n_angles) {
    int i = blockIdx.x * blockDim.x + threadIdx.x;
    if (i < n_angles) atomicAdd(&g_acnt[anb[2 * (size_t)i]], 1u);
}

// ---- K3: angle GEMM + crystal stats. smem-staged af (uniform LDS broadcast),
//      double-buffered 32-angle tiles, batch-4 P-gather pipeline, no SHFL. ----
__global__ void __launch_bounds__(128) k_angle_main(
        const float* __restrict__ af, const int* __restrict__ anb,
        const int* __restrict__ ca, const float* __restrict__ W,
        int n_angles, int chunk) {
    int ch = threadIdx.x;  // 0..127
    ull w2[20];
#pragma unroll
    for (int kk = 0; kk < 20; kk++)
        w2[kk] = pack2(W[(size_t)(2 * kk) * 128 + ch], W[(size_t)(2 * kk + 1) * 128 + ch]);

    __shared__ __align__(16) ull s_af[2][ATILE * 20];
    __shared__ int s_ii[2][ATILE * 2];
    __shared__ int s_cc[2][ATILE];

    int a0 = blockIdx.x * chunk;
    int aend = min(a0 + chunk, n_angles);
    if (a0 >= aend) return;

    const ull* af2 = (const ull*)af;   // float2 view, n_angles*20 elements
    int maxf2 = n_angles * 20 - 1;
    int maxi  = n_angles - 1;

    // prologue: load tile 0 into buffer 0
    {
#pragma unroll
        for (int r = 0; r < 5; r++) {
            int pos = r * 128 + ch;
            int gidx = min(a0 * 20 + pos, maxf2);
            s_af[0][pos] = __ldg(&af2[gidx]);
        }
        if (ch < 64) s_ii[0][ch] = __ldg(&anb[min(2 * a0 + ch, 2 * maxi + 1)]);
        else if (ch < 96) s_cc[0][ch - 64] = __ldg(&ca[min(a0 + ch - 64, maxi)]);
    }
    __syncthreads();

    float lsum = 0.f, lsq = 0.f;
    int lcnt = 0;
    int curc = __ldg(&ca[a0]);

    int buf = 0;
    for (int base = a0; base < aend; base += ATILE, buf ^= 1) {
        int nb = min(ATILE, aend - base);
        int nbase = base + ATILE;
        bool has_next = nbase < aend;
        // prefetch next tile into registers
        ull raf[5]; int rii = 0, rcc = 0;
        if (has_next) {
#pragma unroll
            for (int r = 0; r < 5; r++) {
                int pos = r * 128 + ch;
                raf[r] = __ldg(&af2[min(nbase * 20 + pos, maxf2)]);
            }
            if (ch < 64) rii = __ldg(&anb[min(2 * nbase + ch, 2 * maxi + 1)]);
            else if (ch < 96) rcc = __ldg(&ca[min(nbase + ch - 64, maxi)]);
        }
        // compute current tile
        for (int b4 = 0; b4 < nb; b4 += 4) {
            int i0[4], i1[4], cc4[4];
            float p0[4], p1[4];
#pragma unroll
            for (int j = 0; j < 4; j++) {
                int idx = min(b4 + j, nb - 1);
                i0[j] = s_ii[buf][2 * idx];
                i1[j] = s_ii[buf][2 * idx + 1];
                cc4[j] = s_cc[buf][idx];
            }
#pragma unroll
            for (int j = 0; j < 4; j++) {
                p0[j] = __ldg(&g_P0[(size_t)i0[j] * 128 + ch]);
                p1[j] = __ldg(&g_P1[(size_t)i1[j] * 128 + ch]);
            }
#pragma unroll
            for (int j = 0; j < 4; j++) {
                if (b4 + j >= nb) break;
                if (cc4[j] != curc) {
                    atomicAdd(&g_csum[curc * 128 + ch], lsum);
                    atomicAdd(&g_csumsq[curc * 128 + ch], lsq);
                    if (ch == 0) atomicAdd(&g_ccnt[curc], (unsigned)lcnt);
                    lsum = 0.f; lsq = 0.f; lcnt = 0; curc = cc4[j];
                }
                const ull* ap = &s_af[buf][(b4 + j) * 20];
                ull acc = 0ull;
#pragma unroll
                for (int kk = 0; kk < 10; kk++) {
                    ulonglong2 a2v = *(const ulonglong2*)&ap[2 * kk];
                    acc = ffma2(a2v.x, w2[2 * kk], acc);
                    acc = ffma2(a2v.y, w2[2 * kk + 1], acc);
                }
                float2 u = unpack2(acc);
                float x = u.x + u.y + p0[j] + p1[j];
                g_gbufh[(size_t)(base + b4 + j) * 128 + ch] = __float2half_rn(x);
                lsum += x; lsq += x * x; lcnt++;
            }
        }
        __syncthreads();
        if (has_next) {
#pragma unroll
            for (int r = 0; r < 5; r++) s_af[buf ^ 1][r * 128 + ch] = raf[r];
            if (ch < 64) s_ii[buf ^ 1][ch] = rii;
            else if (ch < 96) s_cc[buf ^ 1][ch - 64] = rcc;
        }
        __syncthreads();
    }
    atomicAdd(&g_csum[curc * 128 + ch], lsum);
    atomicAdd(&g_csumsq[curc * 128 + ch], lsq);
    if (ch == 0) atomicAdd(&g_ccnt[curc], (unsigned)lcnt);
}

// ---- K4: finalize crystal_norm1 affine ----
__global__ void k_stats1(const float* __restrict__ gn1_g, const float* __restrict__ gn1_b) {
    int c = blockIdx.x, j = threadIdx.x;
    float cnt = fmaxf((float)g_ccnt[c], 1.f);
    float mean = g_csum[c * 128 + j] / cnt;
    float var = fmaxf(g_csumsq[c * 128 + j] / cnt - mean * mean, 0.f);
    float inv = rsqrtf(var + 1e-5f);
    float a = gn1_g[j] * inv;
    g_a1[c * 128 + j] = a;
    g_b1[c * 128 + j] = gn1_b[j] - mean * a;
}

// ---- K5: exclusive scan over counts -> offsets + cursors (single block) ----
__global__ void k_scan(int n_edges) {
    __shared__ unsigned ssum[1024];
    int t = threadIdx.x;
    int per = (n_edges + 1023) >> 10;
    int s = t * per, e = min(s + per, n_edges);
    unsigned local = 0;
    for (int i = s; i < e; i++) local += g_acnt[i];
    ssum[t] = local;
    __syncthreads();
    for (int off = 1; off < 1024; off <<= 1) {
        unsigned v = 0;
        if (t >= off) v = ssum[t - off];
        __syncthreads();
        if (t >= off) ssum[t] += v;
        __syncthreads();
    }
    unsigned run = (t > 0) ? ssum[t - 1] : 0u;
    for (int i = s; i < e; i++) {
        unsigned c = g_acnt[i];
        g_off[i] = run;
        g_curs[i] = run;
        run += c;
    }
    if (t == 1023) g_off[n_edges] = ssum[1023];
}

// ---- K6: fill CSR buckets ----
__global__ void k_fill(const int* __restrict__ anb, int n_angles) {
    int i = blockIdx.x * blockDim.x + threadIdx.x;
    if (i < n_angles) {
        int s = anb[2 * (size_t)i];
        unsigned p = atomicAdd(&g_curs[s], 1u);
        g_bucket[p] = i;
    }
}

// ---- K7: streaming gate: y = filt * relu(norm1(gated)), fp16 in/out ----
__global__ void __launch_bounds__(256) k_gate(const int* __restrict__ ca,
                                              const float* __restrict__ W_mask,
                                              int n_angles) {
    int gw = blockIdx.x * (blockDim.x >> 5) + (threadIdx.x >> 5);
    int lane = threadIdx.x & 31;
    int totalw = gridDim.x * (blockDim.x >> 5);
    int chunk = (n_angles + totalw - 1) / totalw;
    int a0 = gw * chunk, aend = min(a0 + chunk, n_angles);
    if (a0 >= aend) return;
    float4 wm = make_float4(0.f, 0.f, 0.f, 0.f);
    if (lane >= 16) wm = ((const float4*)W_mask)[lane - 16];
    int curc = -1;
    float4 av, bv;
    for (int a = a0; a < aend; a++) {
        int c = __ldg(&ca[a]);
        if (c != curc) {
            curc = c;
            av = *(const float4*)&g_a1[c * 128 + 4 * lane];
            bv = *(const float4*)&g_b1[c * 128 + 4 * lane];
        }
        float4 g4 = ld_half4(&g_gbufh[(size_t)a * 128 + 4 * lane]);
        float x0 = fmaf(g4.x, av.x, bv.x);
        float x1 = fmaf(g4.y, av.y, bv.y);
        float x2 = fmaf(g4.z, av.z, bv.z);
        float x3 = fmaf(g4.w, av.w, bv.w);
        float part = x0 * wm.x + x1 * wm.y + x2 * wm.z + x3 * wm.w;
#pragma unroll
        for (int o = 16; o; o >>= 1) part += __shfl_xor_sync(0xffffffffu, part, o);
        float ex = __expf(2.f * part);
        float filt = 1.f - 2.f / (ex + 1.f);   // tanh
        if (lane < 16) {
            float4 y;
            y.x = filt * fmaxf(x0, 0.f);
            y.y = filt * fmaxf(x1, 0.f);
            y.z = filt * fmaxf(x2, 0.f);
            y.w = filt * fmaxf(x3, 0.f);
            st_half4(&g_yh[(size_t)a * 64 + 4 * lane], y);
        }
    }
}

// ---- K8: per-edge segment-sum of y (fp16) + norm2 stats (ce sorted) ----
__global__ void __launch_bounds__(256) k_gather(const int* __restrict__ ce, int n_edges) {
    int gw = blockIdx.x * (blockDim.x >> 5) + (threadIdx.x >> 5);
    int lane = threadIdx.x & 31;
    int totalw = gridDim.x * (blockDim.x >> 5);
    int chunk = (n_edges + totalw - 1) / totalw;
    int e0 = gw * chunk, eend = min(e0 + chunk, n_edges);
    if (e0 >= eend) return;
    float2 lsum = make_float2(0.f, 0.f), lsq = make_float2(0.f, 0.f);
    int lcnt = 0;
    int curc = __ldg(&ce[e0]);
    for (int e = e0; e < eend; e++) {
        int c = __ldg(&ce[e]);
        if (c != curc) {
            int b = curc * 64 + 2 * lane;
            atomicAdd(&g_esum[b], lsum.x); atomicAdd(&g_esum[b + 1], lsum.y);
            atomicAdd(&g_esumsq[b], lsq.x); atomicAdd(&g_esumsq[b + 1], lsq.y);
            if (lane == 0) atomicAdd(&g_ecnt[curc], (unsigned)lcnt);
            lsum = make_float2(0.f, 0.f); lsq = make_float2(0.f, 0.f);
            lcnt = 0; curc = c;
        }
        unsigned s = g_off[e], t = g_off[e + 1];
        float2 acc = make_float2(0.f, 0.f);
        unsigned p = s;
        for (; p + 2 <= t; p += 2) {
            int a0i = __ldg(&g_bucket[p]);
            int a1i = __ldg(&g_bucket[p + 1]);
            float2 y0 = __half22float2(*(const __half2*)&g_yh[(size_t)a0i * 64 + 2 * lane]);
            float2 y1 = __half22float2(*(const __half2*)&g_yh[(size_t)a1i * 64 + 2 * lane]);
            acc.x += y0.x + y1.x;
            acc.y += y0.y + y1.y;
        }
        if (p < t) {
            int a0i = __ldg(&g_bucket[p]);
            float2 y0 = __half22float2(*(const __half2*)&g_yh[(size_t)a0i * 64 + 2 * lane]);
            acc.x += y0.x; acc.y += y0.y;
        }
        float inv = 1.f / fmaxf((float)(t - s), 1.f);
        float2 v = make_float2(acc.x * inv, acc.y * inv);
        *(float2*)&g_summed[(size_t)e * 64 + 2 * lane] = v;
        lsum.x += v.x; lsum.y += v.y;
        lsq.x += v.x * v.x; lsq.y += v.y * v.y;
        lcnt++;
    }
    int b = curc * 64 + 2 * lane;
    atomicAdd(&g_esum[b], lsum.x); atomicAdd(&g_esum[b + 1], lsum.y);
    atomicAdd(&g_esumsq[b], lsq.x); atomicAdd(&g_esumsq[b + 1], lsq.y);
    if (lane == 0) atomicAdd(&g_ecnt[curc], (unsigned)lcnt);
}

// ---- K9: finalize crystal_norm2 affine ----
__global__ void k_stats2(const float* __restrict__ gn2_g, const float* __restrict__ gn2_b) {
    int c = blockIdx.x, j = threadIdx.x;
    float cnt = fmaxf((float)g_ecnt[c], 1.f);
    float mean = g_esum[c * 64 + j] / cnt;
    float var = fmaxf(g_esumsq[c * 64 + j] / cnt - mean * mean, 0.f);
    float inv = rsqrtf(var + 1e-5f);
    float a = gn2_g[j] * inv;
    g_a2[c * 64 + j] = a;
    g_b2[c * 64 + j] = gn2_b[j] - mean * a;
}

// ---- K10: thread-per-edge residual MLPs, weights via uniform shared broadcasts ----
__global__ void __launch_bounds__(256) k_final(
        const float* __restrict__ nbr, const int* __restrict__ ce,
        const float* __restrict__ W1a, const float* __restrict__ b1a,
        const float* __restrict__ W2a, const float* __restrict__ b2a,
        const float* __restrict__ W1b, const float* __restrict__ b1b,
        const float* __restrict__ W2b, const float* __restrict__ b2b,
        float* __restrict__ out, int n_edges) {
    __shared__ float4 sW1a[512], sW2a[512], sW1b[512], sW2b[512];
    __shared__ float sb1a[32], sb2a[64], sb1b[32], sb2b[64];
    int t = threadIdx.x;
    for (int k = t; k < 512; k += 256) {
        sW1a[k] = ((const float4*)W1a)[k];
        sW2a[k] = ((const float4*)W2a)[k];
        sW1b[k] = ((const float4*)W1b)[k];
        sW2b[k] = ((const float4*)W2b)[k];
    }
    if (t < 32) { sb1a[t] = b1a[t]; sb1b[t] = b1b[t]; }
    if (t < 64) { sb2a[t] = b2a[t]; sb2b[t] = b2b[t]; }
    __syncthreads();
    int e = blockIdx.x * 256 + t;
    if (e >= n_edges) return;

    float h[64];
    int c = __ldg(&ce[e]);
    {
        const float4* s4 = (const float4*)&g_summed[(size_t)e * 64];
        const float4* a4 = (const float4*)&g_a2[c * 64];
        const float4* b4 = (const float4*)&g_b2[c * 64];
#pragma unroll
        for (int i = 0; i < 16; i++) {
            float4 sv = s4[i], av = a4[i], bv = b4[i];
            h[4 * i + 0] = fmaf(sv.x, av.x, bv.x);
            h[4 * i + 1] = fmaf(sv.y, av.y, bv.y);
            h[4 * i + 2] = fmaf(sv.z, av.z, bv.z);
            h[4 * i + 3] = fmaf(sv.w, av.w, bv.w);
        }
    }
    float r[32];
    {
        ull racc[16];
#pragma unroll
        for (int j = 0; j < 16; j++) racc[j] = pack2(sb1a[2 * j], sb1a[2 * j + 1]);
#pragma unroll
        for (int k = 0; k < 64; k++) {
            ull hk = pack2(h[k], h[k]);
#pragma unroll
            for (int j = 0; j < 8; j++) {
                float4 w4 = sW1a[k * 8 + j];
                racc[2 * j]     = ffma2(hk, pack2(w4.x, w4.y), racc[2 * j]);
                racc[2 * j + 1] = ffma2(hk, pack2(w4.z, w4.w), racc[2 * j + 1]);
            }
        }
#pragma unroll
        for (int j = 0; j < 16; j++) {
            float2 u = unpack2(racc[j]);
            r[2 * j] = fmaxf(u.x, 0.f);
            r[2 * j + 1] = fmaxf(u.y, 0.f);
        }
        ull hacc[32];
#pragma unroll
        for (int j = 0; j < 32; j++) hacc[j] = pack2(h[2 * j] + sb2a[2 * j], h[2 * j + 1] + sb2a[2 * j + 1]);
#pragma unroll
        for (int k = 0; k < 32; k++) {
            ull rk = pack2(r[k], r[k]);
#pragma unroll
            for (int j = 0; j < 16; j++) {
                float4 w4 = sW2a[k * 16 + j];
                hacc[2 * j]     = ffma2(rk, pack2(w4.x, w4.y), hacc[2 * j]);
                hacc[2 * j + 1] = ffma2(rk, pack2(w4.z, w4.w), hacc[2 * j + 1]);
            }
        }
#pragma unroll
        for (int j = 0; j < 32; j++) {
            float2 u = unpack2(hacc[j]);
            h[2 * j] = u.x; h[2 * j + 1] = u.y;
        }
    }
    {
        ull racc[16];
#pragma unroll
        for (int j = 0; j < 16; j++) racc[j] = pack2(sb1b[2 * j], sb1b[2 * j + 1]);
#pragma unroll
        for (int k = 0; k < 64; k++) {
            ull hk = pack2(h[k], h[k]);
#pragma unroll
            for (int j = 0; j < 8; j++) {
                float4 w4 = sW1b[k * 8 + j];
                racc[2 * j]     = ffma2(hk, pack2(w4.x, w4.y), racc[2 * j]);
                racc[2 * j + 1] = ffma2(hk, pack2(w4.z, w4.w), racc[2 * j + 1]);
            }
        }
#pragma unroll
        for (int j = 0; j < 16; j++) {
            float2 u = unpack2(racc[j]);
            r[2 * j] = fmaxf(u.x, 0.f);
            r[2 * j + 1] = fmaxf(u.y, 0.f);
        }
        ull hacc[32];
#pragma unroll
        for (int j = 0; j < 32; j++) hacc[j] = pack2(h[2 * j] + sb2b[2 * j], h[2 * j + 1] + sb2b[2 * j + 1]);
#pragma unroll
        for (int k = 0; k < 32; k++) {
            ull rk = pack2(r[k], r[k]);
#pragma unroll
            for (int j = 0; j < 16; j++) {
                float4 w4 = sW2b[k * 16 + j];
                hacc[2 * j]     = ffma2(rk, pack2(w4.x, w4.y), hacc[2 * j]);
                hacc[2 * j + 1] = ffma2(rk, pack2(w4.z, w4.w), hacc[2 * j + 1]);
            }
        }
#pragma unroll
        for (int j = 0; j < 32; j++) {
            float2 u = unpack2(hacc[j]);
            h[2 * j] = u.x; h[2 * j + 1] = u.y;
        }
    }
    {
        const float4* n4 = (const float4*)&nbr[(size_t)e * 64];
        float4* o4 = (float4*)&out[(size_t)e * 64];
#pragma unroll
        for (int i = 0; i < 16; i++) {
            float4 nv = n4[i];
            float4 ov;
            ov.x = 0.7071067811865476f * fmaxf(nv.x + h[4 * i + 0], 0.f);
            ov.y = 0.7071067811865476f * fmaxf(nv.y + h[4 * i + 1], 0.f);
            ov.z = 0.7071067811865476f * fmaxf(nv.z + h[4 * i + 2], 0.f);
            ov.w = 0.7071067811865476f * fmaxf(nv.w + h[4 * i + 3], 0.f);
            o4[i] = ov;
        }
    }
}

extern "C" void kernel_launch(void* const* d_in, const int* in_sizes, int n_in,
                              void* d_out, int out_size) {
    const float* nbr       = (const float*)d_in[0];
    const float* angle_fea = (const float*)d_in[1];
    const int*   anb       = (const int*)d_in[2];
    const int*   ce        = (const int*)d_in[3];
    const int*   ca        = (const int*)d_in[4];
    const float* W_full    = (const float*)d_in[5];
    const float* W_mask    = (const float*)d_in[6];
    const float* gn1_g     = (const float*)d_in[7];
    const float* gn1_b     = (const float*)d_in[8];
    const float* gn2_g     = (const float*)d_in[9];
    const float* gn2_b     = (const float*)d_in[10];
    const float* W1a       = (const float*)d_in[11];
    const float* b1a       = (const float*)d_in[12];
    const float* W2a       = (const float*)d_in[13];
    const float* b2a       = (const float*)d_in[14];
    const float* W1b       = (const float*)d_in[15];
    const float* b1b       = (const float*)d_in[16];
    const float* W2b       = (const float*)d_in[17];
    const float* b2b       = (const float*)d_in[18];
    float* out = (float*)d_out;

    int n_edges  = in_sizes[0] / 64;
    int n_angles = in_sizes[1] / 40;

    k_zero<<<512, 256>>>(n_edges);
    dim3 g1(1024, 2);
    k_precompute<<<g1, 128>>>(nbr, W_full, n_edges);
    k_count<<<(n_angles + 255) / 256, 256>>>(anb, n_angles);
    int nblk = 2048;
    int chunk = ((n_angles + nblk - 1) / nblk + ATILE - 1) / ATILE * ATILE;
    k_angle_main<<<nblk, 128>>>(angle_fea, anb, ca, W_full, n_angles, chunk);
    k_stats1<<<256, 128>>>(gn1_g, gn1_b);
    k_scan<<<1, 1024>>>(n_edges);
    k_fill<<<(n_angles + 255) / 256, 256>>>(anb, n_angles);
    k_gate<<<2048, 256>>>(ca, W_mask, n_angles);
    k_gather<<<1024, 256>>>(ce, n_edges);
    k_stats2<<<256, 64>>>(gn2_g, gn2_b);
    k_final<<<(n_edges + 255) / 256, 256>>>(nbr, ce, W1a, b1a, W2a, b2a,
                                            W1b, b1b, W2b, b2b, out, n_edges);
}

// round 5
// speedup vs baseline: 2.0554x; 1.3016x over previous
#include <cuda_runtime.h>
#include <cuda_fp16.h>
#include <math.h>

#define NE_MAX 200000
#define NA_MAX 1600000
#define ATILE 32
#define SCAN_BLOCKS 256

// ---- static scratch ----
__device__ float g_P0[(size_t)NE_MAX * 128];
__device__ float g_P1[(size_t)NE_MAX * 128];
__device__ __half g_gbufh[(size_t)NA_MAX * 128];
__device__ float g_csum[256 * 128];
__device__ float g_csumsq[256 * 128];
__device__ unsigned g_ccnt[256];
__device__ float g_a1[256 * 128];
__device__ float g_b1[256 * 128];
__device__ float g_summed[(size_t)NE_MAX * 64];
__device__ unsigned g_acnt[NE_MAX];
__device__ unsigned g_off[NE_MAX + 1];
__device__ unsigned g_curs[NE_MAX];
__device__ int g_bucket[NA_MAX];
__device__ unsigned g_blksum[SCAN_BLOCKS];
__device__ unsigned g_blkoff[SCAN_BLOCKS];
__device__ float g_esum[256 * 64];
__device__ float g_esumsq[256 * 64];
__device__ unsigned g_ecnt[256];
__device__ float g_a2[256 * 64];
__device__ float g_b2[256 * 64];

typedef unsigned long long ull;
__device__ __forceinline__ ull ffma2(ull a, ull b, ull c) {
    ull d; asm("fma.rn.f32x2 %0, %1, %2, %3;" : "=l"(d) : "l"(a), "l"(b), "l"(c)); return d;
}
__device__ __forceinline__ ull pack2(float x, float y) {
    ull d; asm("mov.b64 %0, {%1, %2};" : "=l"(d) : "f"(x), "f"(y)); return d;
}
__device__ __forceinline__ float2 unpack2(ull a) {
    float x, y; asm("mov.b64 {%0, %1}, %2;" : "=f"(x), "=f"(y) : "l"(a));
    return make_float2(x, y);
}
__device__ __forceinline__ float4 ld_half4(const __half* p) {
    uint2 u = *(const uint2*)p;
    float2 fa = __half22float2(*(__half2*)&u.x);
    float2 fb = __half22float2(*(__half2*)&u.y);
    return make_float4(fa.x, fa.y, fb.x, fb.y);
}
__device__ __forceinline__ void cp_async8(void* smem, const void* gmem) {
    unsigned s = (unsigned)__cvta_generic_to_shared(smem);
    asm volatile("cp.async.ca.shared.global [%0], [%1], 8;" :: "r"(s), "l"(gmem));
}
__device__ __forceinline__ void cp_async4(void* smem, const void* gmem) {
    unsigned s = (unsigned)__cvta_generic_to_shared(smem);
    asm volatile("cp.async.ca.shared.global [%0], [%1], 4;" :: "r"(s), "l"(gmem));
}
__device__ __forceinline__ void cp_commit() { asm volatile("cp.async.commit_group;" ::: "memory"); }
template <int N>
__device__ __forceinline__ void cp_wait() { asm volatile("cp.async.wait_group %0;" :: "n"(N) : "memory"); }

// ---- K0: zero accumulators ----
__global__ void k_zero(int n_edges) {
    int i = blockIdx.x * blockDim.x + threadIdx.x;
    int stride = gridDim.x * blockDim.x;
    for (int k = i; k < n_edges; k += stride) g_acnt[k] = 0u;
    for (int k = i; k < 256 * 128; k += stride) { g_csum[k] = 0.f; g_csumsq[k] = 0.f; }
    for (int k = i; k < 256 * 64; k += stride) { g_esum[k] = 0.f; g_esumsq[k] = 0.f; }
    for (int k = i; k < 256; k += stride) { g_ccnt[k] = 0u; g_ecnt[k] = 0u; }
}

// ---- K1: P0/P1 = nbr_fea @ W_full halves ----
__global__ void k_precompute(const float* __restrict__ nbr,
                             const float* __restrict__ W_full, int n_edges) {
    int j = threadIdx.x;          // 0..127
    int half = blockIdx.y;
    float w[64];
    const float* wb = W_full + (size_t)(40 + half * 64) * 128 + j;
#pragma unroll
    for (int k = 0; k < 64; k++) w[k] = wb[(size_t)k * 128];
    float* P = half ? g_P1 : g_P0;
    __shared__ float4 snb[2][16];
    int nb = gridDim.x;
    for (int e2 = blockIdx.x * 2; e2 < n_edges; e2 += nb * 2) {
        int g = j >> 6, jj = j & 63;
        int e = e2 + g;
        if (jj < 16 && e < n_edges) snb[g][jj] = ((const float4*)(nbr + (size_t)e * 64))[jj];
        __syncthreads();
#pragma unroll 2
        for (int gg = 0; gg < 2; gg++) {
            int ee = e2 + gg;
            if (ee >= n_edges) break;
            float acc = 0.f;
#pragma unroll
            for (int k = 0; k < 16; k++) {
                float4 v = snb[gg][k];
                acc += v.x * w[4 * k] + v.y * w[4 * k + 1] + v.z * w[4 * k + 2] + v.w * w[4 * k + 3];
            }
            P[(size_t)ee * 128 + j] = acc;
        }
        __syncthreads();
    }
}

// ---- K2: count angles per src edge ----
__global__ void k_count(const int* __restrict__ anb, int n_angles) {
    int i = blockIdx.x * blockDim.x + threadIdx.x;
    if (i < n_angles) atomicAdd(&g_acnt[anb[2 * (size_t)i]], 1u);
}

// ---- K3: angle GEMM + crystal stats. cp.async double-buffered 32-angle tiles. ----
__global__ void __launch_bounds__(128) k_angle_main(
        const float* __restrict__ af, const int* __restrict__ anb,
        const int* __restrict__ ca, const float* __restrict__ W,
        int n_angles, int chunk) {
    int ch = threadIdx.x;  // 0..127
    ull w2[20];
#pragma unroll
    for (int kk = 0; kk < 20; kk++)
        w2[kk] = pack2(W[(size_t)(2 * kk) * 128 + ch], W[(size_t)(2 * kk + 1) * 128 + ch]);

    __shared__ __align__(16) ull s_af[2][ATILE * 20];
    __shared__ int s_ii[2][ATILE * 2];
    __shared__ int s_cc[2][ATILE];

    int a0 = blockIdx.x * chunk;
    int aend = min(a0 + chunk, n_angles);
    if (a0 >= aend) return;

    const ull* af2 = (const ull*)af;
    int maxf2 = n_angles * 20 - 1;
    int maxi  = n_angles - 1;

    // prologue: async-load tile 0 into buffer 0
    {
#pragma unroll
        for (int r = 0; r < 5; r++) {
            int pos = r * 128 + ch;
            cp_async8(&s_af[0][pos], &af2[min(a0 * 20 + pos, maxf2)]);
        }
        if (ch < 64) cp_async4(&s_ii[0][ch], &anb[min(2 * a0 + ch, 2 * maxi + 1)]);
        else if (ch < 96) cp_async4(&s_cc[0][ch - 64], &ca[min(a0 + ch - 64, maxi)]);
        cp_commit();
    }

    float lsum = 0.f, lsq = 0.f;
    int lcnt = 0;
    int curc = __ldg(&ca[a0]);

    int buf = 0;
    for (int base = a0; base < aend; base += ATILE, buf ^= 1) {
        int nb = min(ATILE, aend - base);
        int nbase = base + ATILE;
        bool has_next = nbase < aend;
        if (has_next) {
#pragma unroll
            for (int r = 0; r < 5; r++) {
                int pos = r * 128 + ch;
                cp_async8(&s_af[buf ^ 1][pos], &af2[min(nbase * 20 + pos, maxf2)]);
            }
            if (ch < 64) cp_async4(&s_ii[buf ^ 1][ch], &anb[min(2 * nbase + ch, 2 * maxi + 1)]);
            else if (ch < 96) cp_async4(&s_cc[buf ^ 1][ch - 64], &ca[min(nbase + ch - 64, maxi)]);
            cp_commit();
            cp_wait<1>();
        } else {
            cp_wait<0>();
        }
        __syncthreads();
        for (int b4 = 0; b4 < nb; b4 += 4) {
            int i0[4], i1[4], cc4[4];
            float p0[4], p1[4];
#pragma unroll
            for (int j = 0; j < 4; j++) {
                int idx = min(b4 + j, nb - 1);
                i0[j] = s_ii[buf][2 * idx];
                i1[j] = s_ii[buf][2 * idx + 1];
                cc4[j] = s_cc[buf][idx];
            }
#pragma unroll
            for (int j = 0; j < 4; j++) {
                p0[j] = __ldg(&g_P0[(size_t)i0[j] * 128 + ch]);
                p1[j] = __ldg(&g_P1[(size_t)i1[j] * 128 + ch]);
            }
#pragma unroll
            for (int j = 0; j < 4; j++) {
                if (b4 + j >= nb) break;
                if (cc4[j] != curc) {
                    atomicAdd(&g_csum[curc * 128 + ch], lsum);
                    atomicAdd(&g_csumsq[curc * 128 + ch], lsq);
                    if (ch == 0) atomicAdd(&g_ccnt[curc], (unsigned)lcnt);
                    lsum = 0.f; lsq = 0.f; lcnt = 0; curc = cc4[j];
                }
                const ull* ap = &s_af[buf][(b4 + j) * 20];
                ull acc = 0ull;
#pragma unroll
                for (int kk = 0; kk < 10; kk++) {
                    ulonglong2 a2v = *(const ulonglong2*)&ap[2 * kk];
                    acc = ffma2(a2v.x, w2[2 * kk], acc);
                    acc = ffma2(a2v.y, w2[2 * kk + 1], acc);
                }
                float2 u = unpack2(acc);
                float x = u.x + u.y + p0[j] + p1[j];
                g_gbufh[(size_t)(base + b4 + j) * 128 + ch] = __float2half_rn(x);
                lsum += x; lsq += x * x; lcnt++;
            }
        }
        __syncthreads();
    }
    atomicAdd(&g_csum[curc * 128 + ch], lsum);
    atomicAdd(&g_csumsq[curc * 128 + ch], lsq);
    if (ch == 0) atomicAdd(&g_ccnt[curc], (unsigned)lcnt);
}

// ---- K4: finalize crystal_norm1 affine ----
__global__ void k_stats1(const float* __restrict__ gn1_g, const float* __restrict__ gn1_b) {
    int c = blockIdx.x, j = threadIdx.x;
    float cnt = fmaxf((float)g_ccnt[c], 1.f);
    float mean = g_csum[c * 128 + j] / cnt;
    float var = fmaxf(g_csumsq[c * 128 + j] / cnt - mean * mean, 0.f);
    float inv = rsqrtf(var + 1e-5f);
    float a = gn1_g[j] * inv;
    g_a1[c * 128 + j] = a;
    g_b1[c * 128 + j] = gn1_b[j] - mean * a;
}

// ---- K5a/b/c: parallel exclusive scan over counts ----
__global__ void k_scanA(int n_edges) {
    __shared__ unsigned sred[256];
    int b = blockIdx.x, t = threadIdx.x;
    int per = (n_edges + SCAN_BLOCKS - 1) / SCAN_BLOCKS;
    int s = b * per, e = min(s + per, n_edges);
    unsigned local = 0;
    for (int i = s + t; i < e; i += 256) local += g_acnt[i];
    sred[t] = local;
    __syncthreads();
    for (int off = 128; off; off >>= 1) {
        if (t < off) sred[t] += sred[t + off];
        __syncthreads();
    }
    if (t == 0) g_blksum[b] = sred[0];
}
__global__ void k_scanB(int n_edges) {
    __shared__ unsigned ss[SCAN_BLOCKS];
    int t = threadIdx.x;
    ss[t] = g_blksum[t];
    __syncthreads();
    for (int off = 1; off < SCAN_BLOCKS; off <<= 1) {
        unsigned v = (t >= off) ? ss[t - off] : 0u;
        __syncthreads();
        if (t >= off) ss[t] += v;
        __syncthreads();
    }
    g_blkoff[t] = ss[t] - g_blksum[t];   // exclusive
    if (t == SCAN_BLOCKS - 1) g_off[n_edges] = ss[t];
}
__global__ void k_scanC(int n_edges) {
    __shared__ unsigned ss[256];
    int b = blockIdx.x, t = threadIdx.x;
    int per = (n_edges + SCAN_BLOCKS - 1) / SCAN_BLOCKS;
    int s0 = b * per, e0 = min(s0 + per, n_edges);
    int per2 = (per + 255) / 256;
    int s = s0 + t * per2, e = min(s + per2, e0);
    unsigned local = 0;
    for (int i = s; i < e; i++) local += g_acnt[i];
    ss[t] = local;
    __syncthreads();
    for (int off = 1; off < 256; off <<= 1) {
        unsigned v = (t >= off) ? ss[t - off] : 0u;
        __syncthreads();
        if (t >= off) ss[t] += v;
        __syncthreads();
    }
    unsigned run = g_blkoff[b] + ss[t] - local;
    for (int i = s; i < e; i++) {
        unsigned c = g_acnt[i];
        g_off[i] = run;
        g_curs[i] = run;
        run += c;
    }
}

// ---- K6: fill CSR buckets ----
__global__ void k_fill(const int* __restrict__ anb, int n_angles) {
    int i = blockIdx.x * blockDim.x + threadIdx.x;
    if (i < n_angles) {
        int s = anb[2 * (size_t)i];
        unsigned p = atomicAdd(&g_curs[s], 1u);
        g_bucket[p] = i;
    }
}

// ---- K7: fused gate+gather: per-edge, norm1-apply + gate + segment-sum + norm2 stats ----
__global__ void __launch_bounds__(256) k_gather(const int* __restrict__ ca,
                                                const int* __restrict__ ce,
                                                const float* __restrict__ W_mask,
                                                int n_edges) {
    int gw = blockIdx.x * (blockDim.x >> 5) + (threadIdx.x >> 5);
    int lane = threadIdx.x & 31;
    int totalw = gridDim.x * (blockDim.x >> 5);
    int chunk = (n_edges + totalw - 1) / totalw;
    int e0 = gw * chunk, eend = min(e0 + chunk, n_edges);
    if (e0 >= eend) return;
    float4 wm = make_float4(0.f, 0.f, 0.f, 0.f);
    if (lane >= 16) wm = ((const float4*)W_mask)[lane - 16];
    float4 lsum = make_float4(0.f, 0.f, 0.f, 0.f);
    float4 lsq  = make_float4(0.f, 0.f, 0.f, 0.f);
    int lcnt = 0;
    int curc = __ldg(&ce[e0]);
    for (int e = e0; e < eend; e++) {
        int c = __ldg(&ce[e]);
        if (c != curc) {
            if (lane < 16) {
                int b = curc * 64 + 4 * lane;
                atomicAdd(&g_esum[b + 0], lsum.x); atomicAdd(&g_esum[b + 1], lsum.y);
                atomicAdd(&g_esum[b + 2], lsum.z); atomicAdd(&g_esum[b + 3], lsum.w);
                atomicAdd(&g_esumsq[b + 0], lsq.x); atomicAdd(&g_esumsq[b + 1], lsq.y);
                atomicAdd(&g_esumsq[b + 2], lsq.z); atomicAdd(&g_esumsq[b + 3], lsq.w);
            }
            if (lane == 0) atomicAdd(&g_ecnt[curc], (unsigned)lcnt);
            lsum = make_float4(0.f, 0.f, 0.f, 0.f);
            lsq = make_float4(0.f, 0.f, 0.f, 0.f);
            lcnt = 0; curc = c;
        }
        unsigned s = g_off[e], t = g_off[e + 1];
        float4 acc = make_float4(0.f, 0.f, 0.f, 0.f);
        for (unsigned p = s; p < t; p += 2) {
            bool two = (p + 1 < t);
            int aidA = __ldg(&g_bucket[p]);
            int aidB = two ? __ldg(&g_bucket[p + 1]) : aidA;
            int ccA = __ldg(&ca[aidA]);
            int ccB = __ldg(&ca[aidB]);
            float4 gA = ld_half4(&g_gbufh[(size_t)aidA * 128 + 4 * lane]);
            float4 gB = ld_half4(&g_gbufh[(size_t)aidB * 128 + 4 * lane]);
            float4 aA = *(const float4*)&g_a1[ccA * 128 + 4 * lane];
            float4 bA = *(const float4*)&g_b1[ccA * 128 + 4 * lane];
            float4 aB = *(const float4*)&g_a1[ccB * 128 + 4 * lane];
            float4 bB = *(const float4*)&g_b1[ccB * 128 + 4 * lane];
            float xA0 = fmaf(gA.x, aA.x, bA.x), xA1 = fmaf(gA.y, aA.y, bA.y);
            float xA2 = fmaf(gA.z, aA.z, bA.z), xA3 = fmaf(gA.w, aA.w, bA.w);
            float xB0 = fmaf(gB.x, aB.x, bB.x), xB1 = fmaf(gB.y, aB.y, bB.y);
            float xB2 = fmaf(gB.z, aB.z, bB.z), xB3 = fmaf(gB.w, aB.w, bB.w);
            float pA = xA0 * wm.x + xA1 * wm.y + xA2 * wm.z + xA3 * wm.w;
            float pB = xB0 * wm.x + xB1 * wm.y + xB2 * wm.z + xB3 * wm.w;
#pragma unroll
            for (int o = 16; o; o >>= 1) {
                pA += __shfl_xor_sync(0xffffffffu, pA, o);
                pB += __shfl_xor_sync(0xffffffffu, pB, o);
            }
            float fA = 1.f - 2.f / (__expf(2.f * pA) + 1.f);
            float fB = 1.f - 2.f / (__expf(2.f * pB) + 1.f);
            acc.x += fA * fmaxf(xA0, 0.f);
            acc.y += fA * fmaxf(xA1, 0.f);
            acc.z += fA * fmaxf(xA2, 0.f);
            acc.w += fA * fmaxf(xA3, 0.f);
            if (two) {
                acc.x += fB * fmaxf(xB0, 0.f);
                acc.y += fB * fmaxf(xB1, 0.f);
                acc.z += fB * fmaxf(xB2, 0.f);
                acc.w += fB * fmaxf(xB3, 0.f);
            }
        }
        float inv = 1.f / fmaxf((float)(t - s), 1.f);
        float4 v = make_float4(acc.x * inv, acc.y * inv, acc.z * inv, acc.w * inv);
        if (lane < 16) {
            *(float4*)&g_summed[(size_t)e * 64 + 4 * lane] = v;
            lsum.x += v.x; lsum.y += v.y; lsum.z += v.z; lsum.w += v.w;
            lsq.x += v.x * v.x; lsq.y += v.y * v.y; lsq.z += v.z * v.z; lsq.w += v.w * v.w;
        }
        lcnt++;
    }
    if (lane < 16) {
        int b = curc * 64 + 4 * lane;
        atomicAdd(&g_esum[b + 0], lsum.x); atomicAdd(&g_esum[b + 1], lsum.y);
        atomicAdd(&g_esum[b + 2], lsum.z); atomicAdd(&g_esum[b + 3], lsum.w);
        atomicAdd(&g_esumsq[b + 0], lsq.x); atomicAdd(&g_esumsq[b + 1], lsq.y);
        atomicAdd(&g_esumsq[b + 2], lsq.z); atomicAdd(&g_esumsq[b + 3], lsq.w);
    }
    if (lane == 0) atomicAdd(&g_ecnt[curc], (unsigned)lcnt);
}

// ---- K9: finalize crystal_norm2 affine ----
__global__ void k_stats2(const float* __restrict__ gn2_g, const float* __restrict__ gn2_b) {
    int c = blockIdx.x, j = threadIdx.x;
    float cnt = fmaxf((float)g_ecnt[c], 1.f);
    float mean = g_esum[c * 64 + j] / cnt;
    float var = fmaxf(g_esumsq[c * 64 + j] / cnt - mean * mean, 0.f);
    float inv = rsqrtf(var + 1e-5f);
    float a = gn2_g[j] * inv;
    g_a2[c * 64 + j] = a;
    g_b2[c * 64 + j] = gn2_b[j] - mean * a;
}

// ---- K10: thread-per-edge residual MLPs, weights via uniform shared broadcasts ----
__global__ void __launch_bounds__(256) k_final(
        const float* __restrict__ nbr, const int* __restrict__ ce,
        const float* __restrict__ W1a, const float* __restrict__ b1a,
        const float* __restrict__ W2a, const float* __restrict__ b2a,
        const float* __restrict__ W1b, const float* __restrict__ b1b,
        const float* __restrict__ W2b, const float* __restrict__ b2b,
        float* __restrict__ out, int n_edges) {
    __shared__ float4 sW1a[512], sW2a[512], sW1b[512], sW2b[512];
    __shared__ float sb1a[32], sb2a[64], sb1b[32], sb2b[64];
    int t = threadIdx.x;
    for (int k = t; k < 512; k += 256) {
        sW1a[k] = ((const float4*)W1a)[k];
        sW2a[k] = ((const float4*)W2a)[k];
        sW1b[k] = ((const float4*)W1b)[k];
        sW2b[k] = ((const float4*)W2b)[k];
    }
    if (t < 32) { sb1a[t] = b1a[t]; sb1b[t] = b1b[t]; }
    if (t < 64) { sb2a[t] = b2a[t]; sb2b[t] = b2b[t]; }
    __syncthreads();
    int e = blockIdx.x * 256 + t;
    if (e >= n_edges) return;

    float h[64];
    int c = __ldg(&ce[e]);
    {
        const float4* s4 = (const float4*)&g_summed[(size_t)e * 64];
        const float4* a4 = (const float4*)&g_a2[c * 64];
        const float4* b4 = (const float4*)&g_b2[c * 64];
#pragma unroll
        for (int i = 0; i < 16; i++) {
            float4 sv = s4[i], av = a4[i], bv = b4[i];
            h[4 * i + 0] = fmaf(sv.x, av.x, bv.x);
            h[4 * i + 1] = fmaf(sv.y, av.y, bv.y);
            h[4 * i + 2] = fmaf(sv.z, av.z, bv.z);
            h[4 * i + 3] = fmaf(sv.w, av.w, bv.w);
        }
    }
    float r[32];
    {
        ull racc[16];
#pragma unroll
        for (int j = 0; j < 16; j++) racc[j] = pack2(sb1a[2 * j], sb1a[2 * j + 1]);
#pragma unroll
        for (int k = 0; k < 64; k++) {
            ull hk = pack2(h[k], h[k]);
#pragma unroll
            for (int j = 0; j < 8; j++) {
                float4 w4 = sW1a[k * 8 + j];
                racc[2 * j]     = ffma2(hk, pack2(w4.x, w4.y), racc[2 * j]);
                racc[2 * j + 1] = ffma2(hk, pack2(w4.z, w4.w), racc[2 * j + 1]);
            }
        }
#pragma unroll
        for (int j = 0; j < 16; j++) {
            float2 u = unpack2(racc[j]);
            r[2 * j] = fmaxf(u.x, 0.f);
            r[2 * j + 1] = fmaxf(u.y, 0.f);
        }
        ull hacc[32];
#pragma unroll
        for (int j = 0; j < 32; j++) hacc[j] = pack2(h[2 * j] + sb2a[2 * j], h[2 * j + 1] + sb2a[2 * j + 1]);
#pragma unroll
        for (int k = 0; k < 32; k++) {
            ull rk = pack2(r[k], r[k]);
#pragma unroll
            for (int j = 0; j < 16; j++) {
                float4 w4 = sW2a[k * 16 + j];
                hacc[2 * j]     = ffma2(rk, pack2(w4.x, w4.y), hacc[2 * j]);
                hacc[2 * j + 1] = ffma2(rk, pack2(w4.z, w4.w), hacc[2 * j + 1]);
            }
        }
#pragma unroll
        for (int j = 0; j < 32; j++) {
            float2 u = unpack2(hacc[j]);
            h[2 * j] = u.x; h[2 * j + 1] = u.y;
        }
    }
    {
        ull racc[16];
#pragma unroll
        for (int j = 0; j < 16; j++) racc[j] = pack2(sb1b[2 * j], sb1b[2 * j + 1]);
#pragma unroll
        for (int k = 0; k < 64; k++) {
            ull hk = pack2(h[k], h[k]);
#pragma unroll
            for (int j = 0; j < 8; j++) {
                float4 w4 = sW1b[k * 8 + j];
                racc[2 * j]     = ffma2(hk, pack2(w4.x, w4.y), racc[2 * j]);
                racc[2 * j + 1] = ffma2(hk, pack2(w4.z, w4.w), racc[2 * j + 1]);
            }
        }
#pragma unroll
        for (int j = 0; j < 16; j++) {
            float2 u = unpack2(racc[j]);
            r[2 * j] = fmaxf(u.x, 0.f);
            r[2 * j + 1] = fmaxf(u.y, 0.f);
        }
        ull hacc[32];
#pragma unroll
        for (int j = 0; j < 32; j++) hacc[j] = pack2(h[2 * j] + sb2b[2 * j], h[2 * j + 1] + sb2b[2 * j + 1]);
#pragma unroll
        for (int k = 0; k < 32; k++) {
            ull rk = pack2(r[k], r[k]);
#pragma unroll
            for (int j = 0; j < 16; j++) {
                float4 w4 = sW2b[k * 16 + j];
                hacc[2 * j]     = ffma2(rk, pack2(w4.x, w4.y), hacc[2 * j]);
                hacc[2 * j + 1] = ffma2(rk, pack2(w4.z, w4.w), hacc[2 * j + 1]);
            }
        }
#pragma unroll
        for (int j = 0; j < 32; j++) {
            float2 u = unpack2(hacc[j]);
            h[2 * j] = u.x; h[2 * j + 1] = u.y;
        }
    }
    {
        const float4* n4 = (const float4*)&nbr[(size_t)e * 64];
        float4* o4 = (float4*)&out[(size_t)e * 64];
#pragma unroll
        for (int i = 0; i < 16; i++) {
            float4 nv = n4[i];
            float4 ov;
            ov.x = 0.7071067811865476f * fmaxf(nv.x + h[4 * i + 0], 0.f);
            ov.y = 0.7071067811865476f * fmaxf(nv.y + h[4 * i + 1], 0.f);
            ov.z = 0.7071067811865476f * fmaxf(nv.z + h[4 * i + 2], 0.f);
            ov.w = 0.7071067811865476f * fmaxf(nv.w + h[4 * i + 3], 0.f);
            o4[i] = ov;
        }
    }
}

extern "C" void kernel_launch(void* const* d_in, const int* in_sizes, int n_in,
                              void* d_out, int out_size) {
    const float* nbr       = (const float*)d_in[0];
    const float* angle_fea = (const float*)d_in[1];
    const int*   anb       = (const int*)d_in[2];
    const int*   ce        = (const int*)d_in[3];
    const int*   ca        = (const int*)d_in[4];
    const float* W_full    = (const float*)d_in[5];
    const float* W_mask    = (const float*)d_in[6];
    const float* gn1_g     = (const float*)d_in[7];
    const float* gn1_b     = (const float*)d_in[8];
    const float* gn2_g     = (const float*)d_in[9];
    const float* gn2_b     = (const float*)d_in[10];
    const float* W1a       = (const float*)d_in[11];
    const float* b1a       = (const float*)d_in[12];
    const float* W2a       = (const float*)d_in[13];
    const float* b2a       = (const float*)d_in[14];
    const float* W1b       = (const float*)d_in[15];
    const float* b1b       = (const float*)d_in[16];
    const float* W2b       = (const float*)d_in[17];
    const float* b2b       = (const float*)d_in[18];
    float* out = (float*)d_out;

    int n_edges  = in_sizes[0] / 64;
    int n_angles = in_sizes[1] / 40;

    k_zero<<<512, 256>>>(n_edges);
    dim3 g1(1024, 2);
    k_precompute<<<g1, 128>>>(nbr, W_full, n_edges);
    k_count<<<(n_angles + 255) / 256, 256>>>(anb, n_angles);
    int nblk = 2048;
    int chunk = ((n_angles + nblk - 1) / nblk + ATILE - 1) / ATILE * ATILE;
    k_angle_main<<<nblk, 128>>>(angle_fea, anb, ca, W_full, n_angles, chunk);
    k_stats1<<<256, 128>>>(gn1_g, gn1_b);
    k_scanA<<<SCAN_BLOCKS, 256>>>(n_edges);
    k_scanB<<<1, SCAN_BLOCKS>>>(n_edges);
    k_scanC<<<SCAN_BLOCKS, 256>>>(n_edges);
    k_fill<<<(n_angles + 255) / 256, 256>>>(anb, n_angles);
    k_gather<<<2048, 256>>>(ca, ce, W_mask, n_edges);
    k_stats2<<<256, 64>>>(gn2_g, gn2_b);
    k_final<<<(n_edges + 255) / 256, 256>>>(nbr, ce, W1a, b1a, W2a, b2a,
                                            W1b, b1b, W2b, b2b, out, n_edges);
}